// round 13
// baseline (speedup 1.0000x reference)
#include <cuda_runtime.h>
#include <cuda_fp16.h>
#include <math.h>
#include <stdint.h>

#define B_   64
#define S_   512
#define H_   512
#define E_   1024
#define UV_  2176
#define SD_  128
#define M_   (B_*S_)

typedef __half fp16;

// ---------------- scratch (device globals) ----------------
__device__ __align__(16) fp16  g_xnh[(size_t)M_*H_];
__device__ __align__(16) fp16  g_xnl[(size_t)M_*H_];
__device__ __align__(16) fp16  g_wh [(size_t)UV_*H_];
__device__ __align__(16) fp16  g_wl [(size_t)UV_*H_];
__device__ __align__(16) fp16  g_owh[(size_t)H_*E_];
__device__ __align__(16) fp16  g_uh [(size_t)M_*E_];
__device__ __align__(16) fp16  g_vh [(size_t)M_*E_];      // v [b][t][e]
__device__ __align__(16) float g_base[(size_t)M_*SD_];
__device__ __align__(16) fp16  g_qh[(size_t)M_*SD_];
__device__ __align__(16) fp16  g_ql[(size_t)M_*SD_];
__device__ __align__(16) fp16  g_kh[(size_t)M_*SD_];
__device__ __align__(16) fp16  g_kl[(size_t)M_*SD_];
__device__ __align__(16) fp16  g_p [(size_t)B_*S_*S_];
__device__ __align__(16) fp16  g_gt[(size_t)M_*E_];
__device__ float g_sin[S_*64];
__device__ float g_cos[S_*64];

// ---------------- helpers ----------------
__device__ __forceinline__ uint32_t smem_u32(const void* p) {
    uint32_t a;
    asm("{ .reg .u64 t; cvta.to.shared.u64 t, %1; cvt.u32.u64 %0, t; }" : "=r"(a) : "l"(p));
    return a;
}
__device__ __forceinline__ void cpa16(uint32_t s, const void* g) {
    asm volatile("cp.async.cg.shared.global [%0], [%1], 16;" :: "r"(s), "l"(g));
}
#define CP_COMMIT() asm volatile("cp.async.commit_group;")
#define CP_WAIT(n)  asm volatile("cp.async.wait_group %0;" :: "n"(n) : "memory")

__device__ __forceinline__ void ldm4(uint32_t* r, uint32_t a) {
    asm volatile("ldmatrix.sync.aligned.m8n8.x4.shared.b16 {%0,%1,%2,%3},[%4];"
                 : "=r"(r[0]), "=r"(r[1]), "=r"(r[2]), "=r"(r[3]) : "r"(a));
}
__device__ __forceinline__ void ldm4t(uint32_t* r, uint32_t a) {
    asm volatile("ldmatrix.sync.aligned.m8n8.x4.trans.shared.b16 {%0,%1,%2,%3},[%4];"
                 : "=r"(r[0]), "=r"(r[1]), "=r"(r[2]), "=r"(r[3]) : "r"(a));
}
__device__ __forceinline__ void mma16816(float* d, const uint32_t* a, const uint32_t* b) {
    asm volatile("mma.sync.aligned.m16n8k16.row.col.f32.f16.f16.f32 "
                 "{%0,%1,%2,%3},{%4,%5,%6,%7},{%8,%9},{%0,%1,%2,%3};"
                 : "+f"(d[0]), "+f"(d[1]), "+f"(d[2]), "+f"(d[3])
                 : "r"(a[0]), "r"(a[1]), "r"(a[2]), "r"(a[3]), "r"(b[0]), "r"(b[1]));
}
__device__ __forceinline__ void split2(float x, fp16& h, fp16& l) {
    h = __float2half_rn(x);
    l = __float2half_rn(x - __half2float(h));
}
__device__ __forceinline__ uint32_t packh(fp16 a, fp16 b) {
    return (uint32_t)__half_as_ushort(a) | ((uint32_t)__half_as_ushort(b) << 16);
}

// ---------------- small kernels ----------------
__global__ __launch_bounds__(128) void k_norm(const float* __restrict__ x,
                                              const float* __restrict__ ln_g) {
    int row = blockIdx.x;
    const float4* xr = (const float4*)(x + (size_t)row * H_);
    float4 a = xr[threadIdx.x];
    float ss = a.x*a.x + a.y*a.y + a.z*a.z + a.w*a.w;
    #pragma unroll
    for (int o = 16; o; o >>= 1) ss += __shfl_xor_sync(0xffffffffu, ss, o);
    __shared__ float ws[4];
    if ((threadIdx.x & 31) == 0) ws[threadIdx.x >> 5] = ss;
    __syncthreads();
    float total = ws[0] + ws[1] + ws[2] + ws[3];
    float norm = sqrtf(total * (1.0f / (float)H_));
    float sc = ln_g[0] / fmaxf(norm, 1e-5f);
    float v[4] = {a.x*sc, a.y*sc, a.z*sc, a.w*sc};
    fp16 h[4], l[4];
    #pragma unroll
    for (int i = 0; i < 4; i++) split2(v[i], h[i], l[i]);
    size_t off = (size_t)row * H_ + threadIdx.x * 4;
    *(uint2*)(g_xnh + off) = *(uint2*)h;
    *(uint2*)(g_xnl + off) = *(uint2*)l;
}

__global__ __launch_bounds__(256) void k_split(const float* __restrict__ src,
                                               fp16* __restrict__ dh, fp16* __restrict__ dl,
                                               int n4) {
    int i = blockIdx.x * blockDim.x + threadIdx.x;
    if (i >= n4) return;
    float4 a = ((const float4*)src)[i];
    float v[4] = {a.x, a.y, a.z, a.w};
    fp16 h[4], l[4];
    #pragma unroll
    for (int k = 0; k < 4; k++) split2(v[k], h[k], l[k]);
    *(uint2*)(dh + (size_t)i*4) = *(uint2*)h;
    if (dl) *(uint2*)(dl + (size_t)i*4) = *(uint2*)l;
}

__global__ void k_sincos() {
    int s = blockIdx.x, d = threadIdx.x;
    double invf_d = pow(10000.0, (double)d / 64.0);
    float invf = (float)invf_d;
    float arg = (float)s * invf;
    double a = (double)arg;
    g_sin[s*64 + d] = (float)sin(a);
    g_cos[s*64 + d] = (float)cos(a);
}

__global__ __launch_bounds__(64) void k_rope(const float* __restrict__ gamma,
                                             const float* __restrict__ beta) {
    int row = blockIdx.x;
    int s = row & (S_ - 1);
    int d = threadIdx.x;
    const float* base = g_base + (size_t)row * SD_;
    float b1 = base[d], b2 = base[d + 64];
    float sn = g_sin[s*64 + d], cs = g_cos[s*64 + d];
    float x1 = b1 * gamma[d]      + beta[d];
    float x2 = b2 * gamma[d + 64] + beta[d + 64];
    float q0 = x1*cs - x2*sn, q1 = x2*cs + x1*sn;
    float y1 = b1 * gamma[128 + d]      + beta[128 + d];
    float y2 = b2 * gamma[128 + 64 + d] + beta[128 + 64 + d];
    float k0 = y1*cs - y2*sn, k1 = y2*cs + y1*sn;
    size_t o = (size_t)row * SD_;
    fp16 h, l;
    split2(q0, h, l); g_qh[o+d] = h;    g_ql[o+d] = l;
    split2(q1, h, l); g_qh[o+d+64] = h; g_ql[o+d+64] = l;
    split2(k0, h, l); g_kh[o+d] = h;    g_kl[o+d] = l;
    split2(k1, h, l); g_kh[o+d+64] = h; g_kl[o+d+64] = l;
}

// =================================================================
// mma.sync fp16 GEMM: 128x128 CTA tile, 8 warps (4m x 2n), BK=32,
// 3-buffer cp.async rotation, ONE barrier per stage (writes to buffer
// (s+2)%3 == (s-1)%3 are ordered behind the top-of-stage-s barrier,
// which guarantees all warps finished reading it at stage s-1).
// Load-issue position and CP_WAIT structure identical to the proven R9.
// MODE 1: D = Ah*Bh ; MODE 2: += Ah*Bl ; MODE 3: += Al*Bh
// EPI: 0=uv  1=qk  2=pv(B [k][n] + ldmatrix.trans)  3=out
// =================================================================
#define KPAD   40
#define ARR_B  (128*KPAD*2)    // 10240
#define BUF_B  (4*ARR_B)       // 40960 per stage (generic layout)
#define SMEMSZ (3*BUF_B)       // 122880
#define BT_ROW 272
#define BT_ARR (32*BT_ROW)     // 8704
#define BUF2_B (ARR_B + BT_ARR)
#define SMEMSZ2 (3*BUF2_B)     // 56832

template<int EPI, int MODE>
__global__ __launch_bounds__(256) void k_gemm(const float* __restrict__ aux,
                                              const float* __restrict__ aux2,
                                              float* __restrict__ fout,
                                              int bn0) {
    constexpr int LD = (EPI==0) ? 512 : (EPI==1) ? 128 : (EPI==2) ? 512 : 1024;
    constexpr int NS = LD / 32;
    constexpr bool BLO   = (MODE >= 2);
    constexpr bool THREE = (MODE >= 3);
    constexpr bool BT    = (EPI == 2);
    constexpr uint32_t BUFSZ = BT ? BUF2_B : BUF_B;

    extern __shared__ __align__(16) char smem[];
    const uint32_t sb = smem_u32(smem);
    const int tid = threadIdx.x, wid = tid >> 5, lane = tid & 31;
    const int bm = blockIdx.y * 128, bn = bn0 + blockIdx.x * 128, bz = blockIdx.z;

    const fp16 *Ah, *Al, *Bh, *Bl;
    if (EPI == 0)      { Ah = g_xnh; Al = g_xnl; Bh = g_wh;  Bl = g_wl; }
    else if (EPI == 1) { size_t o = (size_t)bz*S_*SD_;
                         Ah = g_qh+o; Al = g_ql+o; Bh = g_kh+o; Bl = g_kl+o; }
    else if (EPI == 2) { Ah = g_p + (size_t)bz*S_*S_; Al = Ah;
                         Bh = g_vh + (size_t)bz*S_*E_; Bl = Bh; }
    else               { Ah = g_gt; Al = g_gt; Bh = g_owh; Bl = g_owh; }

    const int lrow = tid >> 1;
    const int lc   = (tid & 1) * 16;
    const fp16* gAh = Ah + (size_t)(bm + lrow) * LD + lc;
    const fp16* gAl = Al + (size_t)(bm + lrow) * LD + lc;
    const fp16* gBh = Bh + (size_t)(bn + lrow) * LD + lc;
    const fp16* gBl = Bl + (size_t)(bn + lrow) * LD + lc;
    const uint32_t arow = lrow * (KPAD*2) + lc * 2;
    const int btrow = tid >> 3;
    const int btcol = (tid & 7) * 32;
    const fp16* gBt = (EPI == 2) ? Bh + btcol/2 + bn : nullptr;

    auto load_stage = [&](int s, int bf) {
        const uint32_t st = sb + bf * BUFSZ;
        const int off = s * 32;
        if (BT) {
            cpa16(st + arow, gAh + off);
            cpa16(st + arow + 16, gAh + off + 8);
            const uint32_t bd = st + ARR_B + btrow * BT_ROW + btcol;
            const fp16* gsrc = gBt + (size_t)(off + btrow) * E_;
            cpa16(bd, gsrc); cpa16(bd + 16, gsrc + 8);
        } else {
            cpa16(st + arow, gAh + off); cpa16(st + arow + 16, gAh + off + 8);
            if (THREE) {
                cpa16(st + 1*ARR_B + arow, gAl + off);
                cpa16(st + 1*ARR_B + arow + 16, gAl + off + 8);
            }
            cpa16(st + 2*ARR_B + arow, gBh + off);
            cpa16(st + 2*ARR_B + arow + 16, gBh + off + 8);
            if (BLO) {
                cpa16(st + 3*ARR_B + arow, gBl + off);
                cpa16(st + 3*ARR_B + arow + 16, gBl + off + 8);
            }
        }
    };

    load_stage(0, 0); CP_COMMIT();
    load_stage(1, 1); CP_COMMIT();

    const int am = (wid & 3) * 32;
    const int an = (wid >> 2) * 64;
    float acc[2][8][4];
    #pragma unroll
    for (int mt = 0; mt < 2; mt++)
        #pragma unroll
        for (int nt = 0; nt < 8; nt++)
            #pragma unroll
            for (int j = 0; j < 4; j++) acc[mt][nt][j] = 0.f;

    const int a_row = am + (lane & 15);
    const int a_col = (lane >> 4) * 8;
    const int b_row = an + ((lane >> 4) & 1) * 8 + (lane & 7);
    const int b_col = ((lane >> 3) & 1) * 8;
    const int bt_k = lane & 15;
    const int bt_n = (lane >> 4) * 8;

    int bf = 0;   // buffer index of stage s (rotates mod 3)
    for (int s = 0; s < NS; s++) {
        if (s + 1 < NS) { CP_WAIT(1); } else { CP_WAIT(0); }
        __syncthreads();    // single barrier per stage
        const uint32_t bufb = sb + bf * BUFSZ;
        #pragma unroll
        for (int kk = 0; kk < 32; kk += 16) {
            uint32_t ah[2][4], al[2][4];
            #pragma unroll
            for (int mt = 0; mt < 2; mt++) {
                uint32_t ad = bufb + (a_row + mt*16) * (KPAD*2) + (kk + a_col) * 2;
                ldm4(ah[mt], ad);
                if (THREE) ldm4(al[mt], ad + ARR_B);
            }
            uint32_t bh[8][2], bl[8][2];
            #pragma unroll
            for (int n2 = 0; n2 < 4; n2++) {
                uint32_t r[4];
                if (BT) {
                    uint32_t bd = bufb + ARR_B + (kk + bt_k) * BT_ROW
                                  + (an + n2*16 + bt_n) * 2;
                    ldm4t(r, bd);
                    bh[n2*2][0]=r[0]; bh[n2*2][1]=r[1]; bh[n2*2+1][0]=r[2]; bh[n2*2+1][1]=r[3];
                } else {
                    uint32_t bd = bufb + 2*ARR_B + (b_row + n2*16) * (KPAD*2) + (kk + b_col) * 2;
                    ldm4(r, bd);
                    bh[n2*2][0]=r[0]; bh[n2*2][1]=r[1]; bh[n2*2+1][0]=r[2]; bh[n2*2+1][1]=r[3];
                    if (BLO) {
                        ldm4(r, bd + ARR_B);
                        bl[n2*2][0]=r[0]; bl[n2*2][1]=r[1]; bl[n2*2+1][0]=r[2]; bl[n2*2+1][1]=r[3];
                    }
                }
            }
            #pragma unroll
            for (int mt = 0; mt < 2; mt++)
                #pragma unroll
                for (int nt = 0; nt < 8; nt++) {
                    mma16816(acc[mt][nt], ah[mt], bh[nt]);
                    if (BLO)   mma16816(acc[mt][nt], ah[mt], bl[nt]);
                    if (THREE) mma16816(acc[mt][nt], al[mt], bh[nt]);
                }
        }
        // issue stage s+2 into buffer (s+2)%3 == (s-1)%3 — safe: the barrier
        // at the top of THIS stage ordered all reads of that buffer before us.
        if (s + 2 < NS) {
            int b2 = bf + 2; if (b2 >= 3) b2 -= 3;
            load_stage(s + 2, b2); CP_COMMIT();
        }
        if (++bf == 3) bf = 0;
    }

    // -------- epilogue --------
    const int r4 = lane >> 2, c2 = (lane & 3) * 2;
    #pragma unroll
    for (int mt = 0; mt < 2; mt++)
        #pragma unroll
        for (int half = 0; half < 2; half++) {
            const int row = bm + am + mt*16 + half*8 + r4;
            #pragma unroll
            for (int nt = 0; nt < 8; nt++) {
                const int col = bn + an + nt*8 + c2;
                float v0 = acc[mt][nt][half*2 + 0];
                float v1 = acc[mt][nt][half*2 + 1];

                if (EPI == 0) {
                    float a0 = v0 + aux[col], a1 = v1 + aux[col+1];
                    a0 = a0 / (1.0f + expf(-a0));
                    a1 = a1 / (1.0f + expf(-a1));
                    if (col < E_)
                        *(uint32_t*)(g_uh + (size_t)row*E_ + col) =
                            packh(__float2half_rn(a0), __float2half_rn(a1));
                    else if (col < 2*E_)
                        *(uint32_t*)(g_vh + (size_t)row*E_ + (col - E_)) =
                            packh(__float2half_rn(a0), __float2half_rn(a1));
                    else
                        *(float2*)(g_base + (size_t)row*SD_ + (col - 2*E_)) = make_float2(a0, a1);
                } else if (EPI == 1) {
                    float a0 = (v0 + aux[col     - row + (S_-1)]) / 11.313708498984761f;
                    float a1 = (v1 + aux[col + 1 - row + (S_-1)]) / 11.313708498984761f;
                    a0 = fmaxf(a0, 0.f); a1 = fmaxf(a1, 0.f);
                    a0 *= a0; a1 *= a1;
                    size_t o = (size_t)bz*S_*S_ + (size_t)row*S_ + col;
                    *(uint32_t*)(g_p + o) = packh(__float2half_rn(a0), __float2half_rn(a1));
                } else if (EPI == 2) {
                    size_t rr = (size_t)bz*S_ + row;
                    __half2 u2 = *(const __half2*)(g_uh + rr*E_ + col);
                    float a0 = v0 * __half2float(u2.x), a1 = v1 * __half2float(u2.y);
                    *(uint32_t*)(g_gt + rr*E_ + col) = packh(__float2half_rn(a0), __float2half_rn(a1));
                } else {
                    size_t o = (size_t)row*H_ + col;
                    float a0 = v0 + aux[col]     + aux2[o];
                    float a1 = v1 + aux[col + 1] + aux2[o + 1];
                    *(float2*)(fout + o) = make_float2(a0, a1);
                }
            }
        }
}

// ---------------- launch ----------------
extern "C" void kernel_launch(void* const* d_in, const int* in_sizes, int n_in,
                              void* d_out, int out_size) {
    const float* x    = (const float*)d_in[0];
    const float* ln_g = (const float*)d_in[1];
    const float* uv_w = (const float*)d_in[2];
    const float* uv_b = (const float*)d_in[3];
    const float* gam  = (const float*)d_in[4];
    const float* bet  = (const float*)d_in[5];
    const float* wb   = (const float*)d_in[6];
    const float* o_w  = (const float*)d_in[7];
    const float* o_b  = (const float*)d_in[8];
    float* out = (float*)d_out;

    static cudaStream_t s1 = nullptr;
    static cudaEvent_t e_fork, e_aux, e_xn, e_qk;
    static bool init_done = false;
    if (!init_done) {
        cudaFuncSetAttribute(k_gemm<0,1>, cudaFuncAttributeMaxDynamicSharedMemorySize, SMEMSZ);
        cudaFuncSetAttribute(k_gemm<0,3>, cudaFuncAttributeMaxDynamicSharedMemorySize, SMEMSZ);
        cudaFuncSetAttribute(k_gemm<1,3>, cudaFuncAttributeMaxDynamicSharedMemorySize, SMEMSZ);
        cudaFuncSetAttribute(k_gemm<2,1>, cudaFuncAttributeMaxDynamicSharedMemorySize, SMEMSZ2);
        cudaFuncSetAttribute(k_gemm<3,1>, cudaFuncAttributeMaxDynamicSharedMemorySize, SMEMSZ);
        cudaStreamCreateWithFlags(&s1, cudaStreamNonBlocking);
        cudaEventCreateWithFlags(&e_fork, cudaEventDisableTiming);
        cudaEventCreateWithFlags(&e_aux,  cudaEventDisableTiming);
        cudaEventCreateWithFlags(&e_xn,   cudaEventDisableTiming);
        cudaEventCreateWithFlags(&e_qk,   cudaEventDisableTiming);
        init_done = true;
    }

    fp16 *wh, *wl, *owh;
    cudaGetSymbolAddress((void**)&wh,  g_wh);
    cudaGetSymbolAddress((void**)&wl,  g_wl);
    cudaGetSymbolAddress((void**)&owh, g_owh);

    // fork side stream
    cudaEventRecord(e_fork, 0);
    cudaStreamWaitEvent(s1, e_fork, 0);

    // side: sincos + o_w split (independent prologue)
    k_sincos<<<S_, 64, 0, s1>>>();
    k_split <<<(H_*E_/4 + 255)/256, 256, 0, s1>>>(o_w, owh, nullptr, H_*E_/4);
    cudaEventRecord(e_aux, s1);

    // main: norm + uv_w split, then the long uv-main GEMM
    k_norm  <<<M_, 128>>>(x, ln_g);
    k_split <<<(UV_*H_/4 + 255)/256, 256>>>(uv_w, wh, wl, UV_*H_/4);
    cudaEventRecord(e_xn, 0);
    k_gemm<0,1><<<dim3(16, M_/128), 256, SMEMSZ>>>(uv_b, nullptr, nullptr, 0);

    // side: uv_base (3-pass) -> rope -> qk, overlapped with uv-main
    cudaStreamWaitEvent(s1, e_xn, 0);
    k_gemm<0,3><<<dim3(1, M_/128), 256, SMEMSZ, s1>>>(uv_b, nullptr, nullptr, 2048);
    k_rope  <<<M_, 64, 0, s1>>>(gam, bet);
    k_gemm<1,3><<<dim3(S_/128, S_/128, B_), 256, SMEMSZ, s1>>>(wb, nullptr, nullptr, 0);
    cudaEventRecord(e_qk, s1);

    // join: pv needs qk (P) + uv-main (u, v)
    cudaStreamWaitEvent(0, e_qk, 0);
    k_gemm<2,1><<<dim3(E_/128, S_/128, B_), 256, SMEMSZ2>>>(nullptr, nullptr, nullptr, 0);

    // join: out needs o_w split
    cudaStreamWaitEvent(0, e_aux, 0);
    k_gemm<3,1><<<dim3(H_/128, M_/128), 256, SMEMSZ>>>(o_b, x, out, 0);
}

// round 14
// speedup vs baseline: 1.1948x; 1.1948x over previous
#include <cuda_runtime.h>
#include <cuda_fp16.h>
#include <math.h>
#include <stdint.h>

#define B_   64
#define S_   512
#define H_   512
#define E_   1024
#define UV_  2176
#define SD_  128
#define M_   (B_*S_)

typedef __half fp16;

// ---------------- scratch (device globals) ----------------
__device__ __align__(16) fp16  g_xnh[(size_t)M_*H_];
__device__ __align__(16) fp16  g_xnl[(size_t)M_*H_];
__device__ __align__(16) fp16  g_wh [(size_t)UV_*H_];
__device__ __align__(16) fp16  g_wl [(size_t)UV_*H_];
__device__ __align__(16) fp16  g_owh[(size_t)H_*E_];
__device__ __align__(16) fp16  g_uh [(size_t)M_*E_];
__device__ __align__(16) fp16  g_vh [(size_t)M_*E_];      // v [b][t][e]
__device__ __align__(16) float g_base[(size_t)M_*SD_];
__device__ __align__(16) fp16  g_qh[(size_t)M_*SD_];
__device__ __align__(16) fp16  g_ql[(size_t)M_*SD_];
__device__ __align__(16) fp16  g_kh[(size_t)M_*SD_];
__device__ __align__(16) fp16  g_kl[(size_t)M_*SD_];
__device__ __align__(16) fp16  g_p [(size_t)B_*S_*S_];
__device__ __align__(16) fp16  g_gt[(size_t)M_*E_];
__device__ float g_sin[S_*64];
__device__ float g_cos[S_*64];

// ---------------- helpers ----------------
__device__ __forceinline__ uint32_t smem_u32(const void* p) {
    uint32_t a;
    asm("{ .reg .u64 t; cvta.to.shared.u64 t, %1; cvt.u32.u64 %0, t; }" : "=r"(a) : "l"(p));
    return a;
}
__device__ __forceinline__ void cpa16(uint32_t s, const void* g) {
    asm volatile("cp.async.cg.shared.global [%0], [%1], 16;" :: "r"(s), "l"(g));
}
#define CP_COMMIT() asm volatile("cp.async.commit_group;")
#define CP_WAIT(n)  asm volatile("cp.async.wait_group %0;" :: "n"(n) : "memory")

__device__ __forceinline__ void ldm4(uint32_t* r, uint32_t a) {
    asm volatile("ldmatrix.sync.aligned.m8n8.x4.shared.b16 {%0,%1,%2,%3},[%4];"
                 : "=r"(r[0]), "=r"(r[1]), "=r"(r[2]), "=r"(r[3]) : "r"(a));
}
__device__ __forceinline__ void ldm4t(uint32_t* r, uint32_t a) {
    asm volatile("ldmatrix.sync.aligned.m8n8.x4.trans.shared.b16 {%0,%1,%2,%3},[%4];"
                 : "=r"(r[0]), "=r"(r[1]), "=r"(r[2]), "=r"(r[3]) : "r"(a));
}
__device__ __forceinline__ void mma16816(float* d, const uint32_t* a, const uint32_t* b) {
    asm volatile("mma.sync.aligned.m16n8k16.row.col.f32.f16.f16.f32 "
                 "{%0,%1,%2,%3},{%4,%5,%6,%7},{%8,%9},{%0,%1,%2,%3};"
                 : "+f"(d[0]), "+f"(d[1]), "+f"(d[2]), "+f"(d[3])
                 : "r"(a[0]), "r"(a[1]), "r"(a[2]), "r"(a[3]), "r"(b[0]), "r"(b[1]));
}
__device__ __forceinline__ void split2(float x, fp16& h, fp16& l) {
    h = __float2half_rn(x);
    l = __float2half_rn(x - __half2float(h));
}
__device__ __forceinline__ uint32_t packh(fp16 a, fp16 b) {
    return (uint32_t)__half_as_ushort(a) | ((uint32_t)__half_as_ushort(b) << 16);
}

// ---------------- small kernels ----------------
__global__ __launch_bounds__(128) void k_norm(const float* __restrict__ x,
                                              const float* __restrict__ ln_g) {
    int row = blockIdx.x;
    const float4* xr = (const float4*)(x + (size_t)row * H_);
    float4 a = xr[threadIdx.x];
    float ss = a.x*a.x + a.y*a.y + a.z*a.z + a.w*a.w;
    #pragma unroll
    for (int o = 16; o; o >>= 1) ss += __shfl_xor_sync(0xffffffffu, ss, o);
    __shared__ float ws[4];
    if ((threadIdx.x & 31) == 0) ws[threadIdx.x >> 5] = ss;
    __syncthreads();
    float total = ws[0] + ws[1] + ws[2] + ws[3];
    float norm = sqrtf(total * (1.0f / (float)H_));
    float sc = ln_g[0] / fmaxf(norm, 1e-5f);
    float v[4] = {a.x*sc, a.y*sc, a.z*sc, a.w*sc};
    fp16 h[4], l[4];
    #pragma unroll
    for (int i = 0; i < 4; i++) split2(v[i], h[i], l[i]);
    size_t off = (size_t)row * H_ + threadIdx.x * 4;
    *(uint2*)(g_xnh + off) = *(uint2*)h;
    *(uint2*)(g_xnl + off) = *(uint2*)l;
}

__global__ __launch_bounds__(256) void k_split(const float* __restrict__ src,
                                               fp16* __restrict__ dh, fp16* __restrict__ dl,
                                               int n4) {
    int i = blockIdx.x * blockDim.x + threadIdx.x;
    if (i >= n4) return;
    float4 a = ((const float4*)src)[i];
    float v[4] = {a.x, a.y, a.z, a.w};
    fp16 h[4], l[4];
    #pragma unroll
    for (int k = 0; k < 4; k++) split2(v[k], h[k], l[k]);
    *(uint2*)(dh + (size_t)i*4) = *(uint2*)h;
    if (dl) *(uint2*)(dl + (size_t)i*4) = *(uint2*)l;
}

__global__ void k_sincos() {
    int s = blockIdx.x, d = threadIdx.x;
    double invf_d = pow(10000.0, (double)d / 64.0);
    float invf = (float)invf_d;
    float arg = (float)s * invf;
    double a = (double)arg;
    g_sin[s*64 + d] = (float)sin(a);
    g_cos[s*64 + d] = (float)cos(a);
}

__global__ __launch_bounds__(64) void k_rope(const float* __restrict__ gamma,
                                             const float* __restrict__ beta) {
    int row = blockIdx.x;
    int s = row & (S_ - 1);
    int d = threadIdx.x;
    const float* base = g_base + (size_t)row * SD_;
    float b1 = base[d], b2 = base[d + 64];
    float sn = g_sin[s*64 + d], cs = g_cos[s*64 + d];
    float x1 = b1 * gamma[d]      + beta[d];
    float x2 = b2 * gamma[d + 64] + beta[d + 64];
    float q0 = x1*cs - x2*sn, q1 = x2*cs + x1*sn;
    float y1 = b1 * gamma[128 + d]      + beta[128 + d];
    float y2 = b2 * gamma[128 + 64 + d] + beta[128 + 64 + d];
    float k0 = y1*cs - y2*sn, k1 = y2*cs + y1*sn;
    size_t o = (size_t)row * SD_;
    fp16 h, l;
    split2(q0, h, l); g_qh[o+d] = h;    g_ql[o+d] = l;
    split2(q1, h, l); g_qh[o+d+64] = h; g_ql[o+d+64] = l;
    split2(k0, h, l); g_kh[o+d] = h;    g_kl[o+d] = l;
    split2(k1, h, l); g_kh[o+d+64] = h; g_kl[o+d+64] = l;
}

// =================================================================
// mma.sync fp16 GEMM (R9 configuration — FROZEN, proven 785us):
// 128x128 CTA tile, 8 warps (4m x 2n), BK=32, 2-stage cp.async,
// two barriers per stage; pv uses [k][n] B tile + ldmatrix.trans.
// MODE 1: D = Ah*Bh ; MODE 2: += Ah*Bl ; MODE 3: += Al*Bh
// EPI: 0=uv  1=qk  2=pv  3=out
// =================================================================
#define KPAD   40
#define ARR_B  (128*KPAD*2)    // 10240
#define BUF_B  (4*ARR_B)       // 40960
#define SMEMSZ (2*BUF_B)       // 81920
#define BT_ROW 272
#define BT_ARR (32*BT_ROW)     // 8704
#define BUF2_B (ARR_B + BT_ARR)
#define SMEMSZ2 (2*BUF2_B)     // 37888

template<int EPI, int MODE>
__global__ __launch_bounds__(256) void k_gemm(const float* __restrict__ aux,
                                              const float* __restrict__ aux2,
                                              float* __restrict__ fout,
                                              int bn0) {
    constexpr int LD = (EPI==0) ? 512 : (EPI==1) ? 128 : (EPI==2) ? 512 : 1024;
    constexpr int NS = LD / 32;
    constexpr bool BLO   = (MODE >= 2);
    constexpr bool THREE = (MODE >= 3);
    constexpr bool BT    = (EPI == 2);

    extern __shared__ __align__(16) char smem[];
    const uint32_t sb = smem_u32(smem);
    const int tid = threadIdx.x, wid = tid >> 5, lane = tid & 31;
    const int bm = blockIdx.y * 128, bn = bn0 + blockIdx.x * 128, bz = blockIdx.z;

    const fp16 *Ah, *Al, *Bh, *Bl;
    if (EPI == 0)      { Ah = g_xnh; Al = g_xnl; Bh = g_wh;  Bl = g_wl; }
    else if (EPI == 1) { size_t o = (size_t)bz*S_*SD_;
                         Ah = g_qh+o; Al = g_ql+o; Bh = g_kh+o; Bl = g_kl+o; }
    else if (EPI == 2) { Ah = g_p + (size_t)bz*S_*S_; Al = Ah;
                         Bh = g_vh + (size_t)bz*S_*E_; Bl = Bh; }
    else               { Ah = g_gt; Al = g_gt; Bh = g_owh; Bl = g_owh; }

    const int lrow = tid >> 1;
    const int lc   = (tid & 1) * 16;
    const fp16* gAh = Ah + (size_t)(bm + lrow) * LD + lc;
    const fp16* gAl = Al + (size_t)(bm + lrow) * LD + lc;
    const fp16* gBh = Bh + (size_t)(bn + lrow) * LD + lc;
    const fp16* gBl = Bl + (size_t)(bn + lrow) * LD + lc;
    const uint32_t srowA = sb + lrow * (KPAD*2) + lc * 2;
    const int btrow = tid >> 3;
    const int btcol = (tid & 7) * 32;
    const fp16* gBt = (EPI == 2) ? Bh + btcol/2 + bn : nullptr;

    auto load_stage = [&](int s) {
        if (BT) {
            const uint32_t st = sb + (s & 1) * BUF2_B;
            const int off = s * 32;
            cpa16(st + srowA - sb, gAh + off);
            cpa16(st + srowA - sb + 16, gAh + off + 8);
            const uint32_t bd = st + ARR_B + btrow * BT_ROW + btcol;
            const fp16* gsrc = gBt + (size_t)(off + btrow) * E_;
            cpa16(bd, gsrc); cpa16(bd + 16, gsrc + 8);
        } else {
            const uint32_t d = srowA + (s & 1) * BUF_B;
            const int off = s * 32;
            cpa16(d + 0*ARR_B,      gAh + off); cpa16(d + 0*ARR_B + 16, gAh + off + 8);
            if (THREE) {
                cpa16(d + 1*ARR_B,      gAl + off); cpa16(d + 1*ARR_B + 16, gAl + off + 8);
            }
            cpa16(d + 2*ARR_B,      gBh + off); cpa16(d + 2*ARR_B + 16, gBh + off + 8);
            if (BLO) {
                cpa16(d + 3*ARR_B,      gBl + off); cpa16(d + 3*ARR_B + 16, gBl + off + 8);
            }
        }
    };

    load_stage(0); CP_COMMIT();
    load_stage(1); CP_COMMIT();

    const int am = (wid & 3) * 32;
    const int an = (wid >> 2) * 64;
    float acc[2][8][4];
    #pragma unroll
    for (int mt = 0; mt < 2; mt++)
        #pragma unroll
        for (int nt = 0; nt < 8; nt++)
            #pragma unroll
            for (int j = 0; j < 4; j++) acc[mt][nt][j] = 0.f;

    const int a_row = am + (lane & 15);
    const int a_col = (lane >> 4) * 8;
    const int b_row = an + ((lane >> 4) & 1) * 8 + (lane & 7);
    const int b_col = ((lane >> 3) & 1) * 8;
    const int bt_k = lane & 15;
    const int bt_n = (lane >> 4) * 8;

    for (int s = 0; s < NS; s++) {
        if (s + 1 < NS) { CP_WAIT(1); } else { CP_WAIT(0); }
        __syncthreads();
        const uint32_t bufb = sb + (s & 1) * (BT ? BUF2_B : BUF_B);
        #pragma unroll
        for (int kk = 0; kk < 32; kk += 16) {
            uint32_t ah[2][4], al[2][4];
            #pragma unroll
            for (int mt = 0; mt < 2; mt++) {
                uint32_t ad = bufb + (a_row + mt*16) * (KPAD*2) + (kk + a_col) * 2;
                ldm4(ah[mt], ad);
                if (THREE) ldm4(al[mt], ad + ARR_B);
            }
            uint32_t bh[8][2], bl[8][2];
            #pragma unroll
            for (int n2 = 0; n2 < 4; n2++) {
                uint32_t r[4];
                if (BT) {
                    uint32_t bd = bufb + ARR_B + (kk + bt_k) * BT_ROW
                                  + (an + n2*16 + bt_n) * 2;
                    ldm4t(r, bd);
                    bh[n2*2][0]=r[0]; bh[n2*2][1]=r[1]; bh[n2*2+1][0]=r[2]; bh[n2*2+1][1]=r[3];
                } else {
                    uint32_t bd = bufb + 2*ARR_B + (b_row + n2*16) * (KPAD*2) + (kk + b_col) * 2;
                    ldm4(r, bd);
                    bh[n2*2][0]=r[0]; bh[n2*2][1]=r[1]; bh[n2*2+1][0]=r[2]; bh[n2*2+1][1]=r[3];
                    if (BLO) {
                        ldm4(r, bd + ARR_B);
                        bl[n2*2][0]=r[0]; bl[n2*2][1]=r[1]; bl[n2*2+1][0]=r[2]; bl[n2*2+1][1]=r[3];
                    }
                }
            }
            #pragma unroll
            for (int mt = 0; mt < 2; mt++)
                #pragma unroll
                for (int nt = 0; nt < 8; nt++) {
                    mma16816(acc[mt][nt], ah[mt], bh[nt]);
                    if (BLO)   mma16816(acc[mt][nt], ah[mt], bl[nt]);
                    if (THREE) mma16816(acc[mt][nt], al[mt], bh[nt]);
                }
        }
        __syncthreads();
        if (s + 2 < NS) { load_stage(s + 2); CP_COMMIT(); }
    }

    // -------- epilogue --------
    const int r4 = lane >> 2, c2 = (lane & 3) * 2;
    #pragma unroll
    for (int mt = 0; mt < 2; mt++)
        #pragma unroll
        for (int half = 0; half < 2; half++) {
            const int row = bm + am + mt*16 + half*8 + r4;
            #pragma unroll
            for (int nt = 0; nt < 8; nt++) {
                const int col = bn + an + nt*8 + c2;
                float v0 = acc[mt][nt][half*2 + 0];
                float v1 = acc[mt][nt][half*2 + 1];

                if (EPI == 0) {
                    float a0 = v0 + aux[col], a1 = v1 + aux[col+1];
                    a0 = a0 / (1.0f + expf(-a0));
                    a1 = a1 / (1.0f + expf(-a1));
                    if (col < E_)
                        *(uint32_t*)(g_uh + (size_t)row*E_ + col) =
                            packh(__float2half_rn(a0), __float2half_rn(a1));
                    else if (col < 2*E_)
                        *(uint32_t*)(g_vh + (size_t)row*E_ + (col - E_)) =
                            packh(__float2half_rn(a0), __float2half_rn(a1));
                    else
                        *(float2*)(g_base + (size_t)row*SD_ + (col - 2*E_)) = make_float2(a0, a1);
                } else if (EPI == 1) {
                    float a0 = (v0 + aux[col     - row + (S_-1)]) / 11.313708498984761f;
                    float a1 = (v1 + aux[col + 1 - row + (S_-1)]) / 11.313708498984761f;
                    a0 = fmaxf(a0, 0.f); a1 = fmaxf(a1, 0.f);
                    a0 *= a0; a1 *= a1;
                    size_t o = (size_t)bz*S_*S_ + (size_t)row*S_ + col;
                    *(uint32_t*)(g_p + o) = packh(__float2half_rn(a0), __float2half_rn(a1));
                } else if (EPI == 2) {
                    size_t rr = (size_t)bz*S_ + row;
                    __half2 u2 = *(const __half2*)(g_uh + rr*E_ + col);
                    float a0 = v0 * __half2float(u2.x), a1 = v1 * __half2float(u2.y);
                    *(uint32_t*)(g_gt + rr*E_ + col) = packh(__float2half_rn(a0), __float2half_rn(a1));
                } else {
                    size_t o = (size_t)row*H_ + col;
                    float a0 = v0 + aux[col]     + aux2[o];
                    float a1 = v1 + aux[col + 1] + aux2[o + 1];
                    *(float2*)(fout + o) = make_float2(a0, a1);
                }
            }
        }
}

// ---------------- launch ----------------
extern "C" void kernel_launch(void* const* d_in, const int* in_sizes, int n_in,
                              void* d_out, int out_size) {
    const float* x    = (const float*)d_in[0];
    const float* ln_g = (const float*)d_in[1];
    const float* uv_w = (const float*)d_in[2];
    const float* uv_b = (const float*)d_in[3];
    const float* gam  = (const float*)d_in[4];
    const float* bet  = (const float*)d_in[5];
    const float* wb   = (const float*)d_in[6];
    const float* o_w  = (const float*)d_in[7];
    const float* o_b  = (const float*)d_in[8];
    float* out = (float*)d_out;

    static cudaStream_t s1 = nullptr;
    static cudaEvent_t e_fork, e_wsp, e_aux, e_base, e_qk;
    static bool init_done = false;
    if (!init_done) {
        cudaFuncSetAttribute(k_gemm<0,1>, cudaFuncAttributeMaxDynamicSharedMemorySize, SMEMSZ);
        cudaFuncSetAttribute(k_gemm<0,3>, cudaFuncAttributeMaxDynamicSharedMemorySize, SMEMSZ);
        cudaFuncSetAttribute(k_gemm<1,3>, cudaFuncAttributeMaxDynamicSharedMemorySize, SMEMSZ);
        cudaFuncSetAttribute(k_gemm<2,1>, cudaFuncAttributeMaxDynamicSharedMemorySize, SMEMSZ2);
        cudaFuncSetAttribute(k_gemm<3,1>, cudaFuncAttributeMaxDynamicSharedMemorySize, SMEMSZ);
        cudaStreamCreateWithFlags(&s1, cudaStreamNonBlocking);
        cudaEventCreateWithFlags(&e_fork, cudaEventDisableTiming);
        cudaEventCreateWithFlags(&e_wsp,  cudaEventDisableTiming);
        cudaEventCreateWithFlags(&e_aux,  cudaEventDisableTiming);
        cudaEventCreateWithFlags(&e_base, cudaEventDisableTiming);
        cudaEventCreateWithFlags(&e_qk,   cudaEventDisableTiming);
        init_done = true;
    }

    fp16 *wh, *wl, *owh;
    cudaGetSymbolAddress((void**)&wh,  g_wh);
    cudaGetSymbolAddress((void**)&wl,  g_wl);
    cudaGetSymbolAddress((void**)&owh, g_owh);

    // ---- fork side stream ----
    cudaEventRecord(e_fork, 0);
    cudaStreamWaitEvent(s1, e_fork, 0);

    // side: uv_w split (independent of norm) + sincos + o_w split
    k_split <<<(UV_*H_/4 + 255)/256, 256, 0, s1>>>(uv_w, wh, wl, UV_*H_/4);
    cudaEventRecord(e_wsp, s1);
    k_sincos<<<S_, 64, 0, s1>>>();
    k_split <<<(H_*E_/4 + 255)/256, 256, 0, s1>>>(o_w, owh, nullptr, H_*E_/4);
    cudaEventRecord(e_aux, s1);

    // main: norm (concurrent with side prologue), then uv base (3-pass)
    k_norm  <<<M_, 128>>>(x, ln_g);
    cudaStreamWaitEvent(0, e_wsp, 0);
    k_gemm<0,3><<<dim3(1, M_/128), 256, SMEMSZ>>>(uv_b, nullptr, nullptr, 2048);
    cudaEventRecord(e_base, 0);

    // side: rope (needs base + sincos) then qk — overlapped with uv main
    cudaStreamWaitEvent(s1, e_base, 0);
    k_rope  <<<M_, 64, 0, s1>>>(gam, bet);
    k_gemm<1,3><<<dim3(S_/128, S_/128, B_), 256, SMEMSZ, s1>>>(wb, nullptr, nullptr, 0);
    cudaEventRecord(e_qk, s1);

    // main: uv u/v tiles (1-pass) — runs concurrently with rope+qk
    k_gemm<0,1><<<dim3(16, M_/128), 256, SMEMSZ>>>(uv_b, nullptr, nullptr, 0);

    // join: pv needs qk (P) + uv main (u, v)
    cudaStreamWaitEvent(0, e_qk, 0);
    k_gemm<2,1><<<dim3(E_/128, S_/128, B_), 256, SMEMSZ2>>>(nullptr, nullptr, nullptr, 0);

    // join: out needs o_w split
    cudaStreamWaitEvent(0, e_aux, 0);
    k_gemm<3,1><<<dim3(H_/128, M_/128), 256, SMEMSZ>>>(o_b, x, out, 0);
}

// round 15
// speedup vs baseline: 1.2105x; 1.0132x over previous
#include <cuda_runtime.h>
#include <cuda_fp16.h>
#include <math.h>
#include <stdint.h>

#define B_   64
#define S_   512
#define H_   512
#define E_   1024
#define UV_  2176
#define SD_  128
#define M_   (B_*S_)

typedef __half fp16;

// ---------------- scratch (device globals) ----------------
__device__ __align__(16) fp16  g_xnh[(size_t)M_*H_];
__device__ __align__(16) fp16  g_xnl[(size_t)M_*H_];
__device__ __align__(16) fp16  g_wh [(size_t)UV_*H_];
__device__ __align__(16) fp16  g_wl [(size_t)UV_*H_];
__device__ __align__(16) fp16  g_owh[(size_t)H_*E_];
__device__ __align__(16) fp16  g_uh [(size_t)M_*E_];
__device__ __align__(16) fp16  g_vh [(size_t)M_*E_];      // v [b][t][e]
__device__ __align__(16) float g_base[(size_t)M_*SD_];
__device__ __align__(16) fp16  g_qh[(size_t)M_*SD_];
__device__ __align__(16) fp16  g_kh[(size_t)M_*SD_];
__device__ __align__(16) fp16  g_kl[(size_t)M_*SD_];
__device__ __align__(16) fp16  g_p [(size_t)B_*S_*S_];
__device__ __align__(16) fp16  g_gt[(size_t)M_*E_];
__device__ float g_sin[S_*64];
__device__ float g_cos[S_*64];

// ---------------- helpers ----------------
__device__ __forceinline__ uint32_t smem_u32(const void* p) {
    uint32_t a;
    asm("{ .reg .u64 t; cvta.to.shared.u64 t, %1; cvt.u32.u64 %0, t; }" : "=r"(a) : "l"(p));
    return a;
}
__device__ __forceinline__ void cpa16(uint32_t s, const void* g) {
    asm volatile("cp.async.cg.shared.global [%0], [%1], 16;" :: "r"(s), "l"(g));
}
#define CP_COMMIT() asm volatile("cp.async.commit_group;")
#define CP_WAIT(n)  asm volatile("cp.async.wait_group %0;" :: "n"(n) : "memory")

__device__ __forceinline__ void ldm4(uint32_t* r, uint32_t a) {
    asm volatile("ldmatrix.sync.aligned.m8n8.x4.shared.b16 {%0,%1,%2,%3},[%4];"
                 : "=r"(r[0]), "=r"(r[1]), "=r"(r[2]), "=r"(r[3]) : "r"(a));
}
__device__ __forceinline__ void ldm4t(uint32_t* r, uint32_t a) {
    asm volatile("ldmatrix.sync.aligned.m8n8.x4.trans.shared.b16 {%0,%1,%2,%3},[%4];"
                 : "=r"(r[0]), "=r"(r[1]), "=r"(r[2]), "=r"(r[3]) : "r"(a));
}
__device__ __forceinline__ void mma16816(float* d, const uint32_t* a, const uint32_t* b) {
    asm volatile("mma.sync.aligned.m16n8k16.row.col.f32.f16.f16.f32 "
                 "{%0,%1,%2,%3},{%4,%5,%6,%7},{%8,%9},{%0,%1,%2,%3};"
                 : "+f"(d[0]), "+f"(d[1]), "+f"(d[2]), "+f"(d[3])
                 : "r"(a[0]), "r"(a[1]), "r"(a[2]), "r"(a[3]), "r"(b[0]), "r"(b[1]));
}
__device__ __forceinline__ void split2(float x, fp16& h, fp16& l) {
    h = __float2half_rn(x);
    l = __float2half_rn(x - __half2float(h));
}
__device__ __forceinline__ uint32_t packh(fp16 a, fp16 b) {
    return (uint32_t)__half_as_ushort(a) | ((uint32_t)__half_as_ushort(b) << 16);
}

// ---------------- small kernels ----------------
__global__ __launch_bounds__(128) void k_norm(const float* __restrict__ x,
                                              const float* __restrict__ ln_g) {
    int row = blockIdx.x;
    const float4* xr = (const float4*)(x + (size_t)row * H_);
    float4 a = xr[threadIdx.x];
    float ss = a.x*a.x + a.y*a.y + a.z*a.z + a.w*a.w;
    #pragma unroll
    for (int o = 16; o; o >>= 1) ss += __shfl_xor_sync(0xffffffffu, ss, o);
    __shared__ float ws[4];
    if ((threadIdx.x & 31) == 0) ws[threadIdx.x >> 5] = ss;
    __syncthreads();
    float total = ws[0] + ws[1] + ws[2] + ws[3];
    float norm = sqrtf(total * (1.0f / (float)H_));
    float sc = ln_g[0] / fmaxf(norm, 1e-5f);
    float v[4] = {a.x*sc, a.y*sc, a.z*sc, a.w*sc};
    fp16 h[4], l[4];
    #pragma unroll
    for (int i = 0; i < 4; i++) split2(v[i], h[i], l[i]);
    size_t off = (size_t)row * H_ + threadIdx.x * 4;
    *(uint2*)(g_xnh + off) = *(uint2*)h;
    *(uint2*)(g_xnl + off) = *(uint2*)l;
}

__global__ __launch_bounds__(256) void k_split(const float* __restrict__ src,
                                               fp16* __restrict__ dh, fp16* __restrict__ dl,
                                               int n4) {
    int i = blockIdx.x * blockDim.x + threadIdx.x;
    if (i >= n4) return;
    float4 a = ((const float4*)src)[i];
    float v[4] = {a.x, a.y, a.z, a.w};
    fp16 h[4], l[4];
    #pragma unroll
    for (int k = 0; k < 4; k++) split2(v[k], h[k], l[k]);
    *(uint2*)(dh + (size_t)i*4) = *(uint2*)h;
    if (dl) *(uint2*)(dl + (size_t)i*4) = *(uint2*)l;
}

__global__ void k_sincos() {
    int s = blockIdx.x, d = threadIdx.x;
    double invf_d = pow(10000.0, (double)d / 64.0);
    float invf = (float)invf_d;
    float arg = (float)s * invf;
    double a = (double)arg;
    g_sin[s*64 + d] = (float)sin(a);
    g_cos[s*64 + d] = (float)cos(a);
}

__global__ __launch_bounds__(64) void k_rope(const float* __restrict__ gamma,
                                             const float* __restrict__ beta) {
    int row = blockIdx.x;
    int s = row & (S_ - 1);
    int d = threadIdx.x;
    const float* base = g_base + (size_t)row * SD_;
    float b1 = base[d], b2 = base[d + 64];
    float sn = g_sin[s*64 + d], cs = g_cos[s*64 + d];
    float x1 = b1 * gamma[d]      + beta[d];
    float x2 = b2 * gamma[d + 64] + beta[d + 64];
    float q0 = x1*cs - x2*sn, q1 = x2*cs + x1*sn;
    float y1 = b1 * gamma[128 + d]      + beta[128 + d];
    float y2 = b2 * gamma[128 + 64 + d] + beta[128 + 64 + d];
    float k0 = y1*cs - y2*sn, k1 = y2*cs + y1*sn;
    size_t o = (size_t)row * SD_;
    fp16 h, l;
    // q: hi only (qk GEMM is 2-pass: qh*kh + qh*kl)
    g_qh[o+d]    = __float2half_rn(q0);
    g_qh[o+d+64] = __float2half_rn(q1);
    split2(k0, h, l); g_kh[o+d] = h;    g_kl[o+d] = l;
    split2(k1, h, l); g_kh[o+d+64] = h; g_kl[o+d+64] = l;
}

// =================================================================
// mma.sync fp16 GEMM (R9 configuration — FROZEN, proven 785us):
// 128x128 CTA tile, 8 warps (4m x 2n), BK=32, 2-stage cp.async,
// two barriers per stage; pv uses [k][n] B tile + ldmatrix.trans.
// MODE 1: D = Ah*Bh ; MODE 2: += Ah*Bl ; MODE 3: += Al*Bh
// EPI: 0=uv  1=qk  2=pv  3=out
// =================================================================
#define KPAD   40
#define ARR_B  (128*KPAD*2)    // 10240
#define BUF_B  (4*ARR_B)       // 40960
#define SMEMSZ (2*BUF_B)       // 81920
#define BT_ROW 272
#define BT_ARR (32*BT_ROW)     // 8704
#define BUF2_B (ARR_B + BT_ARR)
#define SMEMSZ2 (2*BUF2_B)     // 37888

template<int EPI, int MODE>
__global__ __launch_bounds__(256) void k_gemm(const float* __restrict__ aux,
                                              const float* __restrict__ aux2,
                                              float* __restrict__ fout,
                                              int bn0) {
    constexpr int LD = (EPI==0) ? 512 : (EPI==1) ? 128 : (EPI==2) ? 512 : 1024;
    constexpr int NS = LD / 32;
    constexpr bool BLO   = (MODE >= 2);
    constexpr bool THREE = (MODE >= 3);
    constexpr bool BT    = (EPI == 2);

    extern __shared__ __align__(16) char smem[];
    const uint32_t sb = smem_u32(smem);
    const int tid = threadIdx.x, wid = tid >> 5, lane = tid & 31;
    const int bm = blockIdx.y * 128, bn = bn0 + blockIdx.x * 128, bz = blockIdx.z;

    const fp16 *Ah, *Al, *Bh, *Bl;
    if (EPI == 0)      { Ah = g_xnh; Al = g_xnl; Bh = g_wh;  Bl = g_wl; }
    else if (EPI == 1) { size_t o = (size_t)bz*S_*SD_;
                         Ah = g_qh+o; Al = g_qh+o; Bh = g_kh+o; Bl = g_kl+o; }
    else if (EPI == 2) { Ah = g_p + (size_t)bz*S_*S_; Al = Ah;
                         Bh = g_vh + (size_t)bz*S_*E_; Bl = Bh; }
    else               { Ah = g_gt; Al = g_gt; Bh = g_owh; Bl = g_owh; }

    const int lrow = tid >> 1;
    const int lc   = (tid & 1) * 16;
    const fp16* gAh = Ah + (size_t)(bm + lrow) * LD + lc;
    const fp16* gAl = Al + (size_t)(bm + lrow) * LD + lc;
    const fp16* gBh = Bh + (size_t)(bn + lrow) * LD + lc;
    const fp16* gBl = Bl + (size_t)(bn + lrow) * LD + lc;
    const uint32_t srowA = sb + lrow * (KPAD*2) + lc * 2;
    const int btrow = tid >> 3;
    const int btcol = (tid & 7) * 32;
    const fp16* gBt = (EPI == 2) ? Bh + btcol/2 + bn : nullptr;

    auto load_stage = [&](int s) {
        if (BT) {
            const uint32_t st = sb + (s & 1) * BUF2_B;
            const int off = s * 32;
            cpa16(st + srowA - sb, gAh + off);
            cpa16(st + srowA - sb + 16, gAh + off + 8);
            const uint32_t bd = st + ARR_B + btrow * BT_ROW + btcol;
            const fp16* gsrc = gBt + (size_t)(off + btrow) * E_;
            cpa16(bd, gsrc); cpa16(bd + 16, gsrc + 8);
        } else {
            const uint32_t d = srowA + (s & 1) * BUF_B;
            const int off = s * 32;
            cpa16(d + 0*ARR_B,      gAh + off); cpa16(d + 0*ARR_B + 16, gAh + off + 8);
            if (THREE) {
                cpa16(d + 1*ARR_B,      gAl + off); cpa16(d + 1*ARR_B + 16, gAl + off + 8);
            }
            cpa16(d + 2*ARR_B,      gBh + off); cpa16(d + 2*ARR_B + 16, gBh + off + 8);
            if (BLO) {
                cpa16(d + 3*ARR_B,      gBl + off); cpa16(d + 3*ARR_B + 16, gBl + off + 8);
            }
        }
    };

    load_stage(0); CP_COMMIT();
    load_stage(1); CP_COMMIT();

    const int am = (wid & 3) * 32;
    const int an = (wid >> 2) * 64;
    float acc[2][8][4];
    #pragma unroll
    for (int mt = 0; mt < 2; mt++)
        #pragma unroll
        for (int nt = 0; nt < 8; nt++)
            #pragma unroll
            for (int j = 0; j < 4; j++) acc[mt][nt][j] = 0.f;

    const int a_row = am + (lane & 15);
    const int a_col = (lane >> 4) * 8;
    const int b_row = an + ((lane >> 4) & 1) * 8 + (lane & 7);
    const int b_col = ((lane >> 3) & 1) * 8;
    const int bt_k = lane & 15;
    const int bt_n = (lane >> 4) * 8;

    for (int s = 0; s < NS; s++) {
        if (s + 1 < NS) { CP_WAIT(1); } else { CP_WAIT(0); }
        __syncthreads();
        const uint32_t bufb = sb + (s & 1) * (BT ? BUF2_B : BUF_B);
        #pragma unroll
        for (int kk = 0; kk < 32; kk += 16) {
            uint32_t ah[2][4], al[2][4];
            #pragma unroll
            for (int mt = 0; mt < 2; mt++) {
                uint32_t ad = bufb + (a_row + mt*16) * (KPAD*2) + (kk + a_col) * 2;
                ldm4(ah[mt], ad);
                if (THREE) ldm4(al[mt], ad + ARR_B);
            }
            uint32_t bh[8][2], bl[8][2];
            #pragma unroll
            for (int n2 = 0; n2 < 4; n2++) {
                uint32_t r[4];
                if (BT) {
                    uint32_t bd = bufb + ARR_B + (kk + bt_k) * BT_ROW
                                  + (an + n2*16 + bt_n) * 2;
                    ldm4t(r, bd);
                    bh[n2*2][0]=r[0]; bh[n2*2][1]=r[1]; bh[n2*2+1][0]=r[2]; bh[n2*2+1][1]=r[3];
                } else {
                    uint32_t bd = bufb + 2*ARR_B + (b_row + n2*16) * (KPAD*2) + (kk + b_col) * 2;
                    ldm4(r, bd);
                    bh[n2*2][0]=r[0]; bh[n2*2][1]=r[1]; bh[n2*2+1][0]=r[2]; bh[n2*2+1][1]=r[3];
                    if (BLO) {
                        ldm4(r, bd + ARR_B);
                        bl[n2*2][0]=r[0]; bl[n2*2][1]=r[1]; bl[n2*2+1][0]=r[2]; bl[n2*2+1][1]=r[3];
                    }
                }
            }
            #pragma unroll
            for (int mt = 0; mt < 2; mt++)
                #pragma unroll
                for (int nt = 0; nt < 8; nt++) {
                    mma16816(acc[mt][nt], ah[mt], bh[nt]);
                    if (BLO)   mma16816(acc[mt][nt], ah[mt], bl[nt]);
                    if (THREE) mma16816(acc[mt][nt], al[mt], bh[nt]);
                }
        }
        __syncthreads();
        if (s + 2 < NS) { load_stage(s + 2); CP_COMMIT(); }
    }

    // -------- epilogue --------
    const int r4 = lane >> 2, c2 = (lane & 3) * 2;
    #pragma unroll
    for (int mt = 0; mt < 2; mt++)
        #pragma unroll
        for (int half = 0; half < 2; half++) {
            const int row = bm + am + mt*16 + half*8 + r4;
            #pragma unroll
            for (int nt = 0; nt < 8; nt++) {
                const int col = bn + an + nt*8 + c2;
                float v0 = acc[mt][nt][half*2 + 0];
                float v1 = acc[mt][nt][half*2 + 1];

                if (EPI == 0) {
                    float a0 = v0 + aux[col], a1 = v1 + aux[col+1];
                    a0 = a0 / (1.0f + expf(-a0));
                    a1 = a1 / (1.0f + expf(-a1));
                    if (col < E_)
                        *(uint32_t*)(g_uh + (size_t)row*E_ + col) =
                            packh(__float2half_rn(a0), __float2half_rn(a1));
                    else if (col < 2*E_)
                        *(uint32_t*)(g_vh + (size_t)row*E_ + (col - E_)) =
                            packh(__float2half_rn(a0), __float2half_rn(a1));
                    else
                        *(float2*)(g_base + (size_t)row*SD_ + (col - 2*E_)) = make_float2(a0, a1);
                } else if (EPI == 1) {
                    float a0 = (v0 + aux[col     - row + (S_-1)]) / 11.313708498984761f;
                    float a1 = (v1 + aux[col + 1 - row + (S_-1)]) / 11.313708498984761f;
                    a0 = fmaxf(a0, 0.f); a1 = fmaxf(a1, 0.f);
                    a0 *= a0; a1 *= a1;
                    size_t o = (size_t)bz*S_*S_ + (size_t)row*S_ + col;
                    *(uint32_t*)(g_p + o) = packh(__float2half_rn(a0), __float2half_rn(a1));
                } else if (EPI == 2) {
                    size_t rr = (size_t)bz*S_ + row;
                    __half2 u2 = *(const __half2*)(g_uh + rr*E_ + col);
                    float a0 = v0 * __half2float(u2.x), a1 = v1 * __half2float(u2.y);
                    *(uint32_t*)(g_gt + rr*E_ + col) = packh(__float2half_rn(a0), __float2half_rn(a1));
                } else {
                    size_t o = (size_t)row*H_ + col;
                    float a0 = v0 + aux[col]     + aux2[o];
                    float a1 = v1 + aux[col + 1] + aux2[o + 1];
                    *(float2*)(fout + o) = make_float2(a0, a1);
                }
            }
        }
}

// ---------------- launch ----------------
extern "C" void kernel_launch(void* const* d_in, const int* in_sizes, int n_in,
                              void* d_out, int out_size) {
    const float* x    = (const float*)d_in[0];
    const float* ln_g = (const float*)d_in[1];
    const float* uv_w = (const float*)d_in[2];
    const float* uv_b = (const float*)d_in[3];
    const float* gam  = (const float*)d_in[4];
    const float* bet  = (const float*)d_in[5];
    const float* wb   = (const float*)d_in[6];
    const float* o_w  = (const float*)d_in[7];
    const float* o_b  = (const float*)d_in[8];
    float* out = (float*)d_out;

    static cudaStream_t s1 = nullptr;
    static cudaEvent_t e_fork, e_wsp, e_aux, e_base, e_qk;
    static bool init_done = false;
    if (!init_done) {
        cudaFuncSetAttribute(k_gemm<0,1>, cudaFuncAttributeMaxDynamicSharedMemorySize, SMEMSZ);
        cudaFuncSetAttribute(k_gemm<0,3>, cudaFuncAttributeMaxDynamicSharedMemorySize, SMEMSZ);
        cudaFuncSetAttribute(k_gemm<1,2>, cudaFuncAttributeMaxDynamicSharedMemorySize, SMEMSZ);
        cudaFuncSetAttribute(k_gemm<2,1>, cudaFuncAttributeMaxDynamicSharedMemorySize, SMEMSZ2);
        cudaFuncSetAttribute(k_gemm<3,1>, cudaFuncAttributeMaxDynamicSharedMemorySize, SMEMSZ);
        cudaStreamCreateWithFlags(&s1, cudaStreamNonBlocking);
        cudaEventCreateWithFlags(&e_fork, cudaEventDisableTiming);
        cudaEventCreateWithFlags(&e_wsp,  cudaEventDisableTiming);
        cudaEventCreateWithFlags(&e_aux,  cudaEventDisableTiming);
        cudaEventCreateWithFlags(&e_base, cudaEventDisableTiming);
        cudaEventCreateWithFlags(&e_qk,   cudaEventDisableTiming);
        init_done = true;
    }

    fp16 *wh, *wl, *owh;
    cudaGetSymbolAddress((void**)&wh,  g_wh);
    cudaGetSymbolAddress((void**)&wl,  g_wl);
    cudaGetSymbolAddress((void**)&owh, g_owh);

    // ---- fork side stream ----
    cudaEventRecord(e_fork, 0);
    cudaStreamWaitEvent(s1, e_fork, 0);

    // side: uv_w split (independent of norm) + sincos + o_w split
    k_split <<<(UV_*H_/4 + 255)/256, 256, 0, s1>>>(uv_w, wh, wl, UV_*H_/4);
    cudaEventRecord(e_wsp, s1);
    k_sincos<<<S_, 64, 0, s1>>>();
    k_split <<<(H_*E_/4 + 255)/256, 256, 0, s1>>>(o_w, owh, nullptr, H_*E_/4);
    cudaEventRecord(e_aux, s1);

    // main: norm (concurrent with side prologue), then uv base (3-pass)
    k_norm  <<<M_, 128>>>(x, ln_g);
    cudaStreamWaitEvent(0, e_wsp, 0);
    k_gemm<0,3><<<dim3(1, M_/128), 256, SMEMSZ>>>(uv_b, nullptr, nullptr, 2048);
    cudaEventRecord(e_base, 0);

    // side: rope (needs base + sincos) then qk (2-pass) — overlapped with uv main
    cudaStreamWaitEvent(s1, e_base, 0);
    k_rope  <<<M_, 64, 0, s1>>>(gam, bet);
    k_gemm<1,2><<<dim3(S_/128, S_/128, B_), 256, SMEMSZ, s1>>>(wb, nullptr, nullptr, 0);
    cudaEventRecord(e_qk, s1);

    // main: uv u/v tiles (1-pass) — runs concurrently with rope+qk
    k_gemm<0,1><<<dim3(16, M_/128), 256, SMEMSZ>>>(uv_b, nullptr, nullptr, 0);

    // join: pv needs qk (P) + uv main (u, v)
    cudaStreamWaitEvent(0, e_qk, 0);
    k_gemm<2,1><<<dim3(E_/128, S_/128, B_), 256, SMEMSZ2>>>(nullptr, nullptr, nullptr, 0);

    // join: out needs o_w split
    cudaStreamWaitEvent(0, e_aux, 0);
    k_gemm<3,1><<<dim3(H_/128, M_/128), 256, SMEMSZ>>>(o_b, x, out, 0);
}

// round 16
// speedup vs baseline: 1.2533x; 1.0353x over previous
#include <cuda_runtime.h>
#include <cuda_fp16.h>
#include <math.h>
#include <stdint.h>

#define B_   64
#define S_   512
#define H_   512
#define E_   1024
#define UV_  2176
#define SD_  128
#define M_   (B_*S_)

typedef __half fp16;

// ---------------- scratch (device globals) ----------------
__device__ __align__(16) fp16  g_xnh[(size_t)M_*H_];
__device__ __align__(16) fp16  g_wh [(size_t)UV_*H_];
__device__ __align__(16) fp16  g_wl [(size_t)UV_*H_];
__device__ __align__(16) fp16  g_owh[(size_t)H_*E_];
__device__ __align__(16) fp16  g_uh [(size_t)M_*E_];
__device__ __align__(16) fp16  g_vh [(size_t)M_*E_];      // v [b][t][e]
__device__ __align__(16) float g_base[(size_t)M_*SD_];
__device__ __align__(16) fp16  g_qh[(size_t)M_*SD_];
__device__ __align__(16) fp16  g_kh[(size_t)M_*SD_];
__device__ __align__(16) fp16  g_p [(size_t)B_*S_*S_];
__device__ __align__(16) fp16  g_gt[(size_t)M_*E_];
__device__ float g_sin[S_*64];
__device__ float g_cos[S_*64];

// ---------------- helpers ----------------
__device__ __forceinline__ uint32_t smem_u32(const void* p) {
    uint32_t a;
    asm("{ .reg .u64 t; cvta.to.shared.u64 t, %1; cvt.u32.u64 %0, t; }" : "=r"(a) : "l"(p));
    return a;
}
__device__ __forceinline__ void cpa16(uint32_t s, const void* g) {
    asm volatile("cp.async.cg.shared.global [%0], [%1], 16;" :: "r"(s), "l"(g));
}
#define CP_COMMIT() asm volatile("cp.async.commit_group;")
#define CP_WAIT(n)  asm volatile("cp.async.wait_group %0;" :: "n"(n) : "memory")

__device__ __forceinline__ void ldm4(uint32_t* r, uint32_t a) {
    asm volatile("ldmatrix.sync.aligned.m8n8.x4.shared.b16 {%0,%1,%2,%3},[%4];"
                 : "=r"(r[0]), "=r"(r[1]), "=r"(r[2]), "=r"(r[3]) : "r"(a));
}
__device__ __forceinline__ void ldm4t(uint32_t* r, uint32_t a) {
    asm volatile("ldmatrix.sync.aligned.m8n8.x4.trans.shared.b16 {%0,%1,%2,%3},[%4];"
                 : "=r"(r[0]), "=r"(r[1]), "=r"(r[2]), "=r"(r[3]) : "r"(a));
}
__device__ __forceinline__ void mma16816(float* d, const uint32_t* a, const uint32_t* b) {
    asm volatile("mma.sync.aligned.m16n8k16.row.col.f32.f16.f16.f32 "
                 "{%0,%1,%2,%3},{%4,%5,%6,%7},{%8,%9},{%0,%1,%2,%3};"
                 : "+f"(d[0]), "+f"(d[1]), "+f"(d[2]), "+f"(d[3])
                 : "r"(a[0]), "r"(a[1]), "r"(a[2]), "r"(a[3]), "r"(b[0]), "r"(b[1]));
}
__device__ __forceinline__ void split2(float x, fp16& h, fp16& l) {
    h = __float2half_rn(x);
    l = __float2half_rn(x - __half2float(h));
}
__device__ __forceinline__ uint32_t packh(fp16 a, fp16 b) {
    return (uint32_t)__half_as_ushort(a) | ((uint32_t)__half_as_ushort(b) << 16);
}

// ---------------- small kernels ----------------
__global__ __launch_bounds__(128) void k_norm(const float* __restrict__ x,
                                              const float* __restrict__ ln_g) {
    int row = blockIdx.x;
    const float4* xr = (const float4*)(x + (size_t)row * H_);
    float4 a = xr[threadIdx.x];
    float ss = a.x*a.x + a.y*a.y + a.z*a.z + a.w*a.w;
    #pragma unroll
    for (int o = 16; o; o >>= 1) ss += __shfl_xor_sync(0xffffffffu, ss, o);
    __shared__ float ws[4];
    if ((threadIdx.x & 31) == 0) ws[threadIdx.x >> 5] = ss;
    __syncthreads();
    float total = ws[0] + ws[1] + ws[2] + ws[3];
    float norm = sqrtf(total * (1.0f / (float)H_));
    float sc = ln_g[0] / fmaxf(norm, 1e-5f);
    fp16 h[4];
    h[0] = __float2half_rn(a.x*sc); h[1] = __float2half_rn(a.y*sc);
    h[2] = __float2half_rn(a.z*sc); h[3] = __float2half_rn(a.w*sc);
    *(uint2*)(g_xnh + (size_t)row * H_ + threadIdx.x * 4) = *(uint2*)h;
}

__global__ __launch_bounds__(256) void k_split(const float* __restrict__ src,
                                               fp16* __restrict__ dh, fp16* __restrict__ dl,
                                               int n4) {
    int i = blockIdx.x * blockDim.x + threadIdx.x;
    if (i >= n4) return;
    float4 a = ((const float4*)src)[i];
    float v[4] = {a.x, a.y, a.z, a.w};
    fp16 h[4], l[4];
    #pragma unroll
    for (int k = 0; k < 4; k++) split2(v[k], h[k], l[k]);
    *(uint2*)(dh + (size_t)i*4) = *(uint2*)h;
    if (dl) *(uint2*)(dl + (size_t)i*4) = *(uint2*)l;
}

__global__ void k_sincos() {
    int s = blockIdx.x, d = threadIdx.x;
    double invf_d = pow(10000.0, (double)d / 64.0);
    float invf = (float)invf_d;
    float arg = (float)s * invf;
    double a = (double)arg;
    g_sin[s*64 + d] = (float)sin(a);
    g_cos[s*64 + d] = (float)cos(a);
}

__global__ __launch_bounds__(64) void k_rope(const float* __restrict__ gamma,
                                             const float* __restrict__ beta) {
    int row = blockIdx.x;
    int s = row & (S_ - 1);
    int d = threadIdx.x;
    const float* base = g_base + (size_t)row * SD_;
    float b1 = base[d], b2 = base[d + 64];
    float sn = g_sin[s*64 + d], cs = g_cos[s*64 + d];
    float x1 = b1 * gamma[d]      + beta[d];
    float x2 = b2 * gamma[d + 64] + beta[d + 64];
    float q0 = x1*cs - x2*sn, q1 = x2*cs + x1*sn;
    float y1 = b1 * gamma[128 + d]      + beta[128 + d];
    float y2 = b2 * gamma[128 + 64 + d] + beta[128 + 64 + d];
    float k0 = y1*cs - y2*sn, k1 = y2*cs + y1*sn;
    size_t o = (size_t)row * SD_;
    // qk GEMM is 1-pass (qh*kh): hi halves only
    g_qh[o+d]    = __float2half_rn(q0);
    g_qh[o+d+64] = __float2half_rn(q1);
    g_kh[o+d]    = __float2half_rn(k0);
    g_kh[o+d+64] = __float2half_rn(k1);
}

// =================================================================
// mma.sync fp16 GEMM (R9 loop — FROZEN):
// 128x128 CTA tile, 8 warps (4m x 2n), BK=32, 2-stage cp.async,
// two barriers per stage; pv uses [k][n] B tile + ldmatrix.trans.
// MODE 1: D = Ah*Bh ; MODE 2: += Ah*Bl ; MODE 3: += Al*Bh
// EPI: 0=uv  1=qk  2=pv  3=out
// =================================================================
#define KPAD   40
#define ARR_B  (128*KPAD*2)    // 10240
#define BUF_B  (4*ARR_B)       // 40960
#define SMEMSZ (2*BUF_B)       // 81920
#define BT_ROW 272
#define BT_ARR (32*BT_ROW)     // 8704
#define BUF2_B (ARR_B + BT_ARR)
#define SMEMSZ2 (2*BUF2_B)     // 37888

template<int EPI, int MODE>
__global__ __launch_bounds__(256) void k_gemm(const float* __restrict__ aux,
                                              const float* __restrict__ aux2,
                                              float* __restrict__ fout,
                                              int bn0) {
    constexpr int LD = (EPI==0) ? 512 : (EPI==1) ? 128 : (EPI==2) ? 512 : 1024;
    constexpr int NS = LD / 32;
    constexpr bool BLO   = (MODE >= 2);
    constexpr bool THREE = (MODE >= 3);
    constexpr bool BT    = (EPI == 2);

    extern __shared__ __align__(16) char smem[];
    const uint32_t sb = smem_u32(smem);
    const int tid = threadIdx.x, wid = tid >> 5, lane = tid & 31;
    const int bm = blockIdx.y * 128, bn = bn0 + blockIdx.x * 128, bz = blockIdx.z;

    const fp16 *Ah, *Al, *Bh, *Bl;
    if (EPI == 0)      { Ah = g_xnh; Al = g_xnh; Bh = g_wh;  Bl = g_wl; }
    else if (EPI == 1) { size_t o = (size_t)bz*S_*SD_;
                         Ah = g_qh+o; Al = g_qh+o; Bh = g_kh+o; Bl = g_kh+o; }
    else if (EPI == 2) { Ah = g_p + (size_t)bz*S_*S_; Al = Ah;
                         Bh = g_vh + (size_t)bz*S_*E_; Bl = Bh; }
    else               { Ah = g_gt; Al = g_gt; Bh = g_owh; Bl = g_owh; }

    const int lrow = tid >> 1;
    const int lc   = (tid & 1) * 16;
    const fp16* gAh = Ah + (size_t)(bm + lrow) * LD + lc;
    const fp16* gAl = Al + (size_t)(bm + lrow) * LD + lc;
    const fp16* gBh = Bh + (size_t)(bn + lrow) * LD + lc;
    const fp16* gBl = Bl + (size_t)(bn + lrow) * LD + lc;
    const uint32_t srowA = sb + lrow * (KPAD*2) + lc * 2;
    const int btrow = tid >> 3;
    const int btcol = (tid & 7) * 32;
    const fp16* gBt = (EPI == 2) ? Bh + btcol/2 + bn : nullptr;

    auto load_stage = [&](int s) {
        if (BT) {
            const uint32_t st = sb + (s & 1) * BUF2_B;
            const int off = s * 32;
            cpa16(st + srowA - sb, gAh + off);
            cpa16(st + srowA - sb + 16, gAh + off + 8);
            const uint32_t bd = st + ARR_B + btrow * BT_ROW + btcol;
            const fp16* gsrc = gBt + (size_t)(off + btrow) * E_;
            cpa16(bd, gsrc); cpa16(bd + 16, gsrc + 8);
        } else {
            const uint32_t d = srowA + (s & 1) * BUF_B;
            const int off = s * 32;
            cpa16(d + 0*ARR_B,      gAh + off); cpa16(d + 0*ARR_B + 16, gAh + off + 8);
            if (THREE) {
                cpa16(d + 1*ARR_B,      gAl + off); cpa16(d + 1*ARR_B + 16, gAl + off + 8);
            }
            cpa16(d + 2*ARR_B,      gBh + off); cpa16(d + 2*ARR_B + 16, gBh + off + 8);
            if (BLO) {
                cpa16(d + 3*ARR_B,      gBl + off); cpa16(d + 3*ARR_B + 16, gBl + off + 8);
            }
        }
    };

    load_stage(0); CP_COMMIT();
    load_stage(1); CP_COMMIT();

    const int am = (wid & 3) * 32;
    const int an = (wid >> 2) * 64;
    float acc[2][8][4];
    #pragma unroll
    for (int mt = 0; mt < 2; mt++)
        #pragma unroll
        for (int nt = 0; nt < 8; nt++)
            #pragma unroll
            for (int j = 0; j < 4; j++) acc[mt][nt][j] = 0.f;

    const int a_row = am + (lane & 15);
    const int a_col = (lane >> 4) * 8;
    const int b_row = an + ((lane >> 4) & 1) * 8 + (lane & 7);
    const int b_col = ((lane >> 3) & 1) * 8;
    const int bt_k = lane & 15;
    const int bt_n = (lane >> 4) * 8;

    for (int s = 0; s < NS; s++) {
        if (s + 1 < NS) { CP_WAIT(1); } else { CP_WAIT(0); }
        __syncthreads();
        const uint32_t bufb = sb + (s & 1) * (BT ? BUF2_B : BUF_B);
        #pragma unroll
        for (int kk = 0; kk < 32; kk += 16) {
            uint32_t ah[2][4], al[2][4];
            #pragma unroll
            for (int mt = 0; mt < 2; mt++) {
                uint32_t ad = bufb + (a_row + mt*16) * (KPAD*2) + (kk + a_col) * 2;
                ldm4(ah[mt], ad);
                if (THREE) ldm4(al[mt], ad + ARR_B);
            }
            uint32_t bh[8][2], bl[8][2];
            #pragma unroll
            for (int n2 = 0; n2 < 4; n2++) {
                uint32_t r[4];
                if (BT) {
                    uint32_t bd = bufb + ARR_B + (kk + bt_k) * BT_ROW
                                  + (an + n2*16 + bt_n) * 2;
                    ldm4t(r, bd);
                    bh[n2*2][0]=r[0]; bh[n2*2][1]=r[1]; bh[n2*2+1][0]=r[2]; bh[n2*2+1][1]=r[3];
                } else {
                    uint32_t bd = bufb + 2*ARR_B + (b_row + n2*16) * (KPAD*2) + (kk + b_col) * 2;
                    ldm4(r, bd);
                    bh[n2*2][0]=r[0]; bh[n2*2][1]=r[1]; bh[n2*2+1][0]=r[2]; bh[n2*2+1][1]=r[3];
                    if (BLO) {
                        ldm4(r, bd + ARR_B);
                        bl[n2*2][0]=r[0]; bl[n2*2][1]=r[1]; bl[n2*2+1][0]=r[2]; bl[n2*2+1][1]=r[3];
                    }
                }
            }
            #pragma unroll
            for (int mt = 0; mt < 2; mt++)
                #pragma unroll
                for (int nt = 0; nt < 8; nt++) {
                    mma16816(acc[mt][nt], ah[mt], bh[nt]);
                    if (BLO)   mma16816(acc[mt][nt], ah[mt], bl[nt]);
                    if (THREE) mma16816(acc[mt][nt], al[mt], bh[nt]);
                }
        }
        __syncthreads();
        if (s + 2 < NS) { load_stage(s + 2); CP_COMMIT(); }
    }

    // -------- epilogue --------
    const int r4 = lane >> 2, c2 = (lane & 3) * 2;
    #pragma unroll
    for (int mt = 0; mt < 2; mt++)
        #pragma unroll
        for (int half = 0; half < 2; half++) {
            const int row = bm + am + mt*16 + half*8 + r4;
            #pragma unroll
            for (int nt = 0; nt < 8; nt++) {
                const int col = bn + an + nt*8 + c2;
                float v0 = acc[mt][nt][half*2 + 0];
                float v1 = acc[mt][nt][half*2 + 1];

                if (EPI == 0) {
                    float a0 = v0 + aux[col], a1 = v1 + aux[col+1];
                    a0 = a0 / (1.0f + expf(-a0));
                    a1 = a1 / (1.0f + expf(-a1));
                    if (col < E_)
                        *(uint32_t*)(g_uh + (size_t)row*E_ + col) =
                            packh(__float2half_rn(a0), __float2half_rn(a1));
                    else if (col < 2*E_)
                        *(uint32_t*)(g_vh + (size_t)row*E_ + (col - E_)) =
                            packh(__float2half_rn(a0), __float2half_rn(a1));
                    else
                        *(float2*)(g_base + (size_t)row*SD_ + (col - 2*E_)) = make_float2(a0, a1);
                } else if (EPI == 1) {
                    float a0 = (v0 + aux[col     - row + (S_-1)]) / 11.313708498984761f;
                    float a1 = (v1 + aux[col + 1 - row + (S_-1)]) / 11.313708498984761f;
                    a0 = fmaxf(a0, 0.f); a1 = fmaxf(a1, 0.f);
                    a0 *= a0; a1 *= a1;
                    size_t o = (size_t)bz*S_*S_ + (size_t)row*S_ + col;
                    *(uint32_t*)(g_p + o) = packh(__float2half_rn(a0), __float2half_rn(a1));
                } else if (EPI == 2) {
                    size_t rr = (size_t)bz*S_ + row;
                    __half2 u2 = *(const __half2*)(g_uh + rr*E_ + col);
                    float a0 = v0 * __half2float(u2.x), a1 = v1 * __half2float(u2.y);
                    *(uint32_t*)(g_gt + rr*E_ + col) = packh(__float2half_rn(a0), __float2half_rn(a1));
                } else {
                    size_t o = (size_t)row*H_ + col;
                    float a0 = v0 + aux[col]     + aux2[o];
                    float a1 = v1 + aux[col + 1] + aux2[o + 1];
                    *(float2*)(fout + o) = make_float2(a0, a1);
                }
            }
        }
}

// ---------------- launch ----------------
extern "C" void kernel_launch(void* const* d_in, const int* in_sizes, int n_in,
                              void* d_out, int out_size) {
    const float* x    = (const float*)d_in[0];
    const float* ln_g = (const float*)d_in[1];
    const float* uv_w = (const float*)d_in[2];
    const float* uv_b = (const float*)d_in[3];
    const float* gam  = (const float*)d_in[4];
    const float* bet  = (const float*)d_in[5];
    const float* wb   = (const float*)d_in[6];
    const float* o_w  = (const float*)d_in[7];
    const float* o_b  = (const float*)d_in[8];
    float* out = (float*)d_out;

    static cudaStream_t s1 = nullptr;
    static cudaEvent_t e_fork, e_wsp, e_aux, e_base, e_qk;
    static bool init_done = false;
    if (!init_done) {
        cudaFuncSetAttribute(k_gemm<0,1>, cudaFuncAttributeMaxDynamicSharedMemorySize, SMEMSZ);
        cudaFuncSetAttribute(k_gemm<0,2>, cudaFuncAttributeMaxDynamicSharedMemorySize, SMEMSZ);
        cudaFuncSetAttribute(k_gemm<1,1>, cudaFuncAttributeMaxDynamicSharedMemorySize, SMEMSZ);
        cudaFuncSetAttribute(k_gemm<2,1>, cudaFuncAttributeMaxDynamicSharedMemorySize, SMEMSZ2);
        cudaFuncSetAttribute(k_gemm<3,1>, cudaFuncAttributeMaxDynamicSharedMemorySize, SMEMSZ);
        cudaStreamCreateWithFlags(&s1, cudaStreamNonBlocking);
        cudaEventCreateWithFlags(&e_fork, cudaEventDisableTiming);
        cudaEventCreateWithFlags(&e_wsp,  cudaEventDisableTiming);
        cudaEventCreateWithFlags(&e_aux,  cudaEventDisableTiming);
        cudaEventCreateWithFlags(&e_base, cudaEventDisableTiming);
        cudaEventCreateWithFlags(&e_qk,   cudaEventDisableTiming);
        init_done = true;
    }

    fp16 *wh, *wl, *owh;
    cudaGetSymbolAddress((void**)&wh,  g_wh);
    cudaGetSymbolAddress((void**)&wl,  g_wl);
    cudaGetSymbolAddress((void**)&owh, g_owh);

    // ---- fork side stream ----
    cudaEventRecord(e_fork, 0);
    cudaStreamWaitEvent(s1, e_fork, 0);

    // side: uv_w split (independent of norm) + sincos + o_w split
    k_split <<<(UV_*H_/4 + 255)/256, 256, 0, s1>>>(uv_w, wh, wl, UV_*H_/4);
    cudaEventRecord(e_wsp, s1);
    k_sincos<<<S_, 64, 0, s1>>>();
    k_split <<<(H_*E_/4 + 255)/256, 256, 0, s1>>>(o_w, owh, nullptr, H_*E_/4);
    cudaEventRecord(e_aux, s1);

    // main: norm (concurrent with side prologue), then uv base (2-pass)
    k_norm  <<<M_, 128>>>(x, ln_g);
    cudaStreamWaitEvent(0, e_wsp, 0);
    k_gemm<0,2><<<dim3(1, M_/128), 256, SMEMSZ>>>(uv_b, nullptr, nullptr, 2048);
    cudaEventRecord(e_base, 0);

    // side: rope (needs base + sincos) then qk (1-pass) — overlapped with uv main
    cudaStreamWaitEvent(s1, e_base, 0);
    k_rope  <<<M_, 64, 0, s1>>>(gam, bet);
    k_gemm<1,1><<<dim3(S_/128, S_/128, B_), 256, SMEMSZ, s1>>>(wb, nullptr, nullptr, 0);
    cudaEventRecord(e_qk, s1);

    // main: uv u/v tiles (1-pass) — runs concurrently with rope+qk
    k_gemm<0,1><<<dim3(16, M_/128), 256, SMEMSZ>>>(uv_b, nullptr, nullptr, 0);

    // join: pv needs qk (P) + uv main (u, v)
    cudaStreamWaitEvent(0, e_qk, 0);
    k_gemm<2,1><<<dim3(E_/128, S_/128, B_), 256, SMEMSZ2>>>(nullptr, nullptr, nullptr, 0);

    // join: out needs o_w split
    cudaStreamWaitEvent(0, e_aux, 0);
    k_gemm<3,1><<<dim3(H_/128, M_/128), 256, SMEMSZ>>>(o_b, x, out, 0);
}

// round 17
// speedup vs baseline: 1.2811x; 1.0222x over previous
#include <cuda_runtime.h>
#include <cuda_fp16.h>
#include <math.h>
#include <stdint.h>

#define B_   64
#define S_   512
#define H_   512
#define E_   1024
#define UV_  2176
#define SD_  128
#define M_   (B_*S_)

typedef __half fp16;

// ---------------- scratch (device globals) ----------------
__device__ __align__(16) fp16  g_xnh[(size_t)M_*H_];
__device__ __align__(16) fp16  g_wh [(size_t)UV_*H_];
__device__ __align__(16) fp16  g_owh[(size_t)H_*E_];
__device__ __align__(16) fp16  g_uh [(size_t)M_*E_];
__device__ __align__(16) fp16  g_vh [(size_t)M_*E_];      // v [b][t][e]
__device__ __align__(16) float g_base[(size_t)M_*SD_];
__device__ __align__(16) fp16  g_qh[(size_t)M_*SD_];
__device__ __align__(16) fp16  g_kh[(size_t)M_*SD_];
__device__ __align__(16) fp16  g_p [(size_t)B_*S_*S_];
__device__ __align__(16) fp16  g_gt[(size_t)M_*E_];
__device__ float g_sin[S_*64];
__device__ float g_cos[S_*64];

// ---------------- helpers ----------------
__device__ __forceinline__ uint32_t smem_u32(const void* p) {
    uint32_t a;
    asm("{ .reg .u64 t; cvta.to.shared.u64 t, %1; cvt.u32.u64 %0, t; }" : "=r"(a) : "l"(p));
    return a;
}
__device__ __forceinline__ void cpa16(uint32_t s, const void* g) {
    asm volatile("cp.async.cg.shared.global [%0], [%1], 16;" :: "r"(s), "l"(g));
}
#define CP_COMMIT() asm volatile("cp.async.commit_group;")
#define CP_WAIT(n)  asm volatile("cp.async.wait_group %0;" :: "n"(n) : "memory")

__device__ __forceinline__ void ldm4(uint32_t* r, uint32_t a) {
    asm volatile("ldmatrix.sync.aligned.m8n8.x4.shared.b16 {%0,%1,%2,%3},[%4];"
                 : "=r"(r[0]), "=r"(r[1]), "=r"(r[2]), "=r"(r[3]) : "r"(a));
}
__device__ __forceinline__ void ldm4t(uint32_t* r, uint32_t a) {
    asm volatile("ldmatrix.sync.aligned.m8n8.x4.trans.shared.b16 {%0,%1,%2,%3},[%4];"
                 : "=r"(r[0]), "=r"(r[1]), "=r"(r[2]), "=r"(r[3]) : "r"(a));
}
__device__ __forceinline__ void mma16816(float* d, const uint32_t* a, const uint32_t* b) {
    asm volatile("mma.sync.aligned.m16n8k16.row.col.f32.f16.f16.f32 "
                 "{%0,%1,%2,%3},{%4,%5,%6,%7},{%8,%9},{%0,%1,%2,%3};"
                 : "+f"(d[0]), "+f"(d[1]), "+f"(d[2]), "+f"(d[3])
                 : "r"(a[0]), "r"(a[1]), "r"(a[2]), "r"(a[3]), "r"(b[0]), "r"(b[1]));
}
__device__ __forceinline__ uint32_t packh(fp16 a, fp16 b) {
    return (uint32_t)__half_as_ushort(a) | ((uint32_t)__half_as_ushort(b) << 16);
}

// ---------------- small kernels ----------------
__global__ __launch_bounds__(128) void k_norm(const float* __restrict__ x,
                                              const float* __restrict__ ln_g) {
    int row = blockIdx.x;
    const float4* xr = (const float4*)(x + (size_t)row * H_);
    float4 a = xr[threadIdx.x];
    float ss = a.x*a.x + a.y*a.y + a.z*a.z + a.w*a.w;
    #pragma unroll
    for (int o = 16; o; o >>= 1) ss += __shfl_xor_sync(0xffffffffu, ss, o);
    __shared__ float ws[4];
    if ((threadIdx.x & 31) == 0) ws[threadIdx.x >> 5] = ss;
    __syncthreads();
    float total = ws[0] + ws[1] + ws[2] + ws[3];
    float norm = sqrtf(total * (1.0f / (float)H_));
    float sc = ln_g[0] / fmaxf(norm, 1e-5f);
    fp16 h[4];
    h[0] = __float2half_rn(a.x*sc); h[1] = __float2half_rn(a.y*sc);
    h[2] = __float2half_rn(a.z*sc); h[3] = __float2half_rn(a.w*sc);
    *(uint2*)(g_xnh + (size_t)row * H_ + threadIdx.x * 4) = *(uint2*)h;
}

// fp32 -> fp16 (hi only)
__global__ __launch_bounds__(256) void k_cvt(const float* __restrict__ src,
                                             fp16* __restrict__ dh, int n4) {
    int i = blockIdx.x * blockDim.x + threadIdx.x;
    if (i >= n4) return;
    float4 a = ((const float4*)src)[i];
    fp16 h[4];
    h[0] = __float2half_rn(a.x); h[1] = __float2half_rn(a.y);
    h[2] = __float2half_rn(a.z); h[3] = __float2half_rn(a.w);
    *(uint2*)(dh + (size_t)i*4) = *(uint2*)h;
}

__global__ void k_sincos() {
    int s = blockIdx.x, d = threadIdx.x;
    double invf_d = pow(10000.0, (double)d / 64.0);
    float invf = (float)invf_d;
    float arg = (float)s * invf;
    double a = (double)arg;
    g_sin[s*64 + d] = (float)sin(a);
    g_cos[s*64 + d] = (float)cos(a);
}

__global__ __launch_bounds__(64) void k_rope(const float* __restrict__ gamma,
                                             const float* __restrict__ beta) {
    int row = blockIdx.x;
    int s = row & (S_ - 1);
    int d = threadIdx.x;
    const float* base = g_base + (size_t)row * SD_;
    float b1 = base[d], b2 = base[d + 64];
    float sn = g_sin[s*64 + d], cs = g_cos[s*64 + d];
    float x1 = b1 * gamma[d]      + beta[d];
    float x2 = b2 * gamma[d + 64] + beta[d + 64];
    float q0 = x1*cs - x2*sn, q1 = x2*cs + x1*sn;
    float y1 = b1 * gamma[128 + d]      + beta[128 + d];
    float y2 = b2 * gamma[128 + 64 + d] + beta[128 + 64 + d];
    float k0 = y1*cs - y2*sn, k1 = y2*cs + y1*sn;
    size_t o = (size_t)row * SD_;
    g_qh[o+d]    = __float2half_rn(q0);
    g_qh[o+d+64] = __float2half_rn(q1);
    g_kh[o+d]    = __float2half_rn(k0);
    g_kh[o+d+64] = __float2half_rn(k1);
}

// =================================================================
// mma.sync fp16 GEMM (R9 loop — FROZEN):
// 128x128 CTA tile, 8 warps (4m x 2n), BK=32, 2-stage cp.async,
// two barriers per stage; pv uses [k][n] B tile + ldmatrix.trans.
// All GEMMs now MODE 1: D = Ah*Bh.
// EPI: 0=uv  1=qk  2=pv  3=out
// =================================================================
#define KPAD   40
#define ARR_B  (128*KPAD*2)    // 10240
#define BUF_B  (4*ARR_B)       // 40960
#define SMEMSZ (2*BUF_B)       // 81920
#define BT_ROW 272
#define BT_ARR (32*BT_ROW)     // 8704
#define BUF2_B (ARR_B + BT_ARR)
#define SMEMSZ2 (2*BUF2_B)     // 37888

template<int EPI, int MODE>
__global__ __launch_bounds__(256) void k_gemm(const float* __restrict__ aux,
                                              const float* __restrict__ aux2,
                                              float* __restrict__ fout,
                                              int bn0) {
    constexpr int LD = (EPI==0) ? 512 : (EPI==1) ? 128 : (EPI==2) ? 512 : 1024;
    constexpr int NS = LD / 32;
    constexpr bool BLO   = (MODE >= 2);
    constexpr bool THREE = (MODE >= 3);
    constexpr bool BT    = (EPI == 2);

    extern __shared__ __align__(16) char smem[];
    const uint32_t sb = smem_u32(smem);
    const int tid = threadIdx.x, wid = tid >> 5, lane = tid & 31;
    const int bm = blockIdx.y * 128, bn = bn0 + blockIdx.x * 128, bz = blockIdx.z;

    const fp16 *Ah, *Al, *Bh, *Bl;
    if (EPI == 0)      { Ah = g_xnh; Al = g_xnh; Bh = g_wh;  Bl = g_wh; }
    else if (EPI == 1) { size_t o = (size_t)bz*S_*SD_;
                         Ah = g_qh+o; Al = g_qh+o; Bh = g_kh+o; Bl = g_kh+o; }
    else if (EPI == 2) { Ah = g_p + (size_t)bz*S_*S_; Al = Ah;
                         Bh = g_vh + (size_t)bz*S_*E_; Bl = Bh; }
    else               { Ah = g_gt; Al = g_gt; Bh = g_owh; Bl = g_owh; }

    const int lrow = tid >> 1;
    const int lc   = (tid & 1) * 16;
    const fp16* gAh = Ah + (size_t)(bm + lrow) * LD + lc;
    const fp16* gAl = Al + (size_t)(bm + lrow) * LD + lc;
    const fp16* gBh = Bh + (size_t)(bn + lrow) * LD + lc;
    const fp16* gBl = Bl + (size_t)(bn + lrow) * LD + lc;
    const uint32_t srowA = sb + lrow * (KPAD*2) + lc * 2;
    const int btrow = tid >> 3;
    const int btcol = (tid & 7) * 32;
    const fp16* gBt = (EPI == 2) ? Bh + btcol/2 + bn : nullptr;

    auto load_stage = [&](int s) {
        if (BT) {
            const uint32_t st = sb + (s & 1) * BUF2_B;
            const int off = s * 32;
            cpa16(st + srowA - sb, gAh + off);
            cpa16(st + srowA - sb + 16, gAh + off + 8);
            const uint32_t bd = st + ARR_B + btrow * BT_ROW + btcol;
            const fp16* gsrc = gBt + (size_t)(off + btrow) * E_;
            cpa16(bd, gsrc); cpa16(bd + 16, gsrc + 8);
        } else {
            const uint32_t d = srowA + (s & 1) * BUF_B;
            const int off = s * 32;
            cpa16(d + 0*ARR_B,      gAh + off); cpa16(d + 0*ARR_B + 16, gAh + off + 8);
            if (THREE) {
                cpa16(d + 1*ARR_B,      gAl + off); cpa16(d + 1*ARR_B + 16, gAl + off + 8);
            }
            cpa16(d + 2*ARR_B,      gBh + off); cpa16(d + 2*ARR_B + 16, gBh + off + 8);
            if (BLO) {
                cpa16(d + 3*ARR_B,      gBl + off); cpa16(d + 3*ARR_B + 16, gBl + off + 8);
            }
        }
    };

    load_stage(0); CP_COMMIT();
    load_stage(1); CP_COMMIT();

    const int am = (wid & 3) * 32;
    const int an = (wid >> 2) * 64;
    float acc[2][8][4];
    #pragma unroll
    for (int mt = 0; mt < 2; mt++)
        #pragma unroll
        for (int nt = 0; nt < 8; nt++)
            #pragma unroll
            for (int j = 0; j < 4; j++) acc[mt][nt][j] = 0.f;

    const int a_row = am + (lane & 15);
    const int a_col = (lane >> 4) * 8;
    const int b_row = an + ((lane >> 4) & 1) * 8 + (lane & 7);
    const int b_col = ((lane >> 3) & 1) * 8;
    const int bt_k = lane & 15;
    const int bt_n = (lane >> 4) * 8;

    for (int s = 0; s < NS; s++) {
        if (s + 1 < NS) { CP_WAIT(1); } else { CP_WAIT(0); }
        __syncthreads();
        const uint32_t bufb = sb + (s & 1) * (BT ? BUF2_B : BUF_B);
        #pragma unroll
        for (int kk = 0; kk < 32; kk += 16) {
            uint32_t ah[2][4], al[2][4];
            #pragma unroll
            for (int mt = 0; mt < 2; mt++) {
                uint32_t ad = bufb + (a_row + mt*16) * (KPAD*2) + (kk + a_col) * 2;
                ldm4(ah[mt], ad);
                if (THREE) ldm4(al[mt], ad + ARR_B);
            }
            uint32_t bh[8][2], bl[8][2];
            #pragma unroll
            for (int n2 = 0; n2 < 4; n2++) {
                uint32_t r[4];
                if (BT) {
                    uint32_t bd = bufb + ARR_B + (kk + bt_k) * BT_ROW
                                  + (an + n2*16 + bt_n) * 2;
                    ldm4t(r, bd);
                    bh[n2*2][0]=r[0]; bh[n2*2][1]=r[1]; bh[n2*2+1][0]=r[2]; bh[n2*2+1][1]=r[3];
                } else {
                    uint32_t bd = bufb + 2*ARR_B + (b_row + n2*16) * (KPAD*2) + (kk + b_col) * 2;
                    ldm4(r, bd);
                    bh[n2*2][0]=r[0]; bh[n2*2][1]=r[1]; bh[n2*2+1][0]=r[2]; bh[n2*2+1][1]=r[3];
                    if (BLO) {
                        ldm4(r, bd + ARR_B);
                        bl[n2*2][0]=r[0]; bl[n2*2][1]=r[1]; bl[n2*2+1][0]=r[2]; bl[n2*2+1][1]=r[3];
                    }
                }
            }
            #pragma unroll
            for (int mt = 0; mt < 2; mt++)
                #pragma unroll
                for (int nt = 0; nt < 8; nt++) {
                    mma16816(acc[mt][nt], ah[mt], bh[nt]);
                    if (BLO)   mma16816(acc[mt][nt], ah[mt], bl[nt]);
                    if (THREE) mma16816(acc[mt][nt], al[mt], bh[nt]);
                }
        }
        __syncthreads();
        if (s + 2 < NS) { load_stage(s + 2); CP_COMMIT(); }
    }

    // -------- epilogue --------
    const int r4 = lane >> 2, c2 = (lane & 3) * 2;
    #pragma unroll
    for (int mt = 0; mt < 2; mt++)
        #pragma unroll
        for (int half = 0; half < 2; half++) {
            const int row = bm + am + mt*16 + half*8 + r4;
            #pragma unroll
            for (int nt = 0; nt < 8; nt++) {
                const int col = bn + an + nt*8 + c2;
                float v0 = acc[mt][nt][half*2 + 0];
                float v1 = acc[mt][nt][half*2 + 1];

                if (EPI == 0) {
                    float a0 = v0 + aux[col], a1 = v1 + aux[col+1];
                    a0 = a0 / (1.0f + expf(-a0));
                    a1 = a1 / (1.0f + expf(-a1));
                    if (col < E_)
                        *(uint32_t*)(g_uh + (size_t)row*E_ + col) =
                            packh(__float2half_rn(a0), __float2half_rn(a1));
                    else if (col < 2*E_)
                        *(uint32_t*)(g_vh + (size_t)row*E_ + (col - E_)) =
                            packh(__float2half_rn(a0), __float2half_rn(a1));
                    else
                        *(float2*)(g_base + (size_t)row*SD_ + (col - 2*E_)) = make_float2(a0, a1);
                } else if (EPI == 1) {
                    float a0 = (v0 + aux[col     - row + (S_-1)]) / 11.313708498984761f;
                    float a1 = (v1 + aux[col + 1 - row + (S_-1)]) / 11.313708498984761f;
                    a0 = fmaxf(a0, 0.f); a1 = fmaxf(a1, 0.f);
                    a0 *= a0; a1 *= a1;
                    size_t o = (size_t)bz*S_*S_ + (size_t)row*S_ + col;
                    *(uint32_t*)(g_p + o) = packh(__float2half_rn(a0), __float2half_rn(a1));
                } else if (EPI == 2) {
                    size_t rr = (size_t)bz*S_ + row;
                    __half2 u2 = *(const __half2*)(g_uh + rr*E_ + col);
                    float a0 = v0 * __half2float(u2.x), a1 = v1 * __half2float(u2.y);
                    *(uint32_t*)(g_gt + rr*E_ + col) = packh(__float2half_rn(a0), __float2half_rn(a1));
                } else {
                    size_t o = (size_t)row*H_ + col;
                    float a0 = v0 + aux[col]     + aux2[o];
                    float a1 = v1 + aux[col + 1] + aux2[o + 1];
                    *(float2*)(fout + o) = make_float2(a0, a1);
                }
            }
        }
}

// ---------------- launch ----------------
extern "C" void kernel_launch(void* const* d_in, const int* in_sizes, int n_in,
                              void* d_out, int out_size) {
    const float* x    = (const float*)d_in[0];
    const float* ln_g = (const float*)d_in[1];
    const float* uv_w = (const float*)d_in[2];
    const float* uv_b = (const float*)d_in[3];
    const float* gam  = (const float*)d_in[4];
    const float* bet  = (const float*)d_in[5];
    const float* wb   = (const float*)d_in[6];
    const float* o_w  = (const float*)d_in[7];
    const float* o_b  = (const float*)d_in[8];
    float* out = (float*)d_out;

    static cudaStream_t s1 = nullptr;
    static cudaEvent_t e_fork, e_wsp, e_aux, e_base, e_qk;
    static bool init_done = false;
    if (!init_done) {
        cudaFuncSetAttribute(k_gemm<0,1>, cudaFuncAttributeMaxDynamicSharedMemorySize, SMEMSZ);
        cudaFuncSetAttribute(k_gemm<1,1>, cudaFuncAttributeMaxDynamicSharedMemorySize, SMEMSZ);
        cudaFuncSetAttribute(k_gemm<2,1>, cudaFuncAttributeMaxDynamicSharedMemorySize, SMEMSZ2);
        cudaFuncSetAttribute(k_gemm<3,1>, cudaFuncAttributeMaxDynamicSharedMemorySize, SMEMSZ);
        cudaStreamCreateWithFlags(&s1, cudaStreamNonBlocking);
        cudaEventCreateWithFlags(&e_fork, cudaEventDisableTiming);
        cudaEventCreateWithFlags(&e_wsp,  cudaEventDisableTiming);
        cudaEventCreateWithFlags(&e_aux,  cudaEventDisableTiming);
        cudaEventCreateWithFlags(&e_base, cudaEventDisableTiming);
        cudaEventCreateWithFlags(&e_qk,   cudaEventDisableTiming);
        init_done = true;
    }

    fp16 *wh, *owh;
    cudaGetSymbolAddress((void**)&wh,  g_wh);
    cudaGetSymbolAddress((void**)&owh, g_owh);

    // ---- fork side stream ----
    cudaEventRecord(e_fork, 0);
    cudaStreamWaitEvent(s1, e_fork, 0);

    // side: uv_w convert (hi only) + sincos + o_w convert
    k_cvt <<<(UV_*H_/4 + 255)/256, 256, 0, s1>>>(uv_w, wh, UV_*H_/4);
    cudaEventRecord(e_wsp, s1);
    k_sincos<<<S_, 64, 0, s1>>>();
    k_cvt <<<(H_*E_/4 + 255)/256, 256, 0, s1>>>(o_w, owh, H_*E_/4);
    cudaEventRecord(e_aux, s1);

    // main: norm (concurrent with side prologue), then uv base (1-pass)
    k_norm  <<<M_, 128>>>(x, ln_g);
    cudaStreamWaitEvent(0, e_wsp, 0);
    k_gemm<0,1><<<dim3(1, M_/128), 256, SMEMSZ>>>(uv_b, nullptr, nullptr, 2048);
    cudaEventRecord(e_base, 0);

    // side: rope (needs base + sincos) then qk (1-pass) — overlapped with uv main
    cudaStreamWaitEvent(s1, e_base, 0);
    k_rope  <<<M_, 64, 0, s1>>>(gam, bet);
    k_gemm<1,1><<<dim3(S_/128, S_/128, B_), 256, SMEMSZ, s1>>>(wb, nullptr, nullptr, 0);
    cudaEventRecord(e_qk, s1);

    // main: uv u/v tiles (1-pass) — runs concurrently with rope+qk
    k_gemm<0,1><<<dim3(16, M_/128), 256, SMEMSZ>>>(uv_b, nullptr, nullptr, 0);

    // join: pv needs qk (P) + uv main (u, v)
    cudaStreamWaitEvent(0, e_qk, 0);
    k_gemm<2,1><<<dim3(E_/128, S_/128, B_), 256, SMEMSZ2>>>(nullptr, nullptr, nullptr, 0);

    // join: out needs o_w convert
    cudaStreamWaitEvent(0, e_aux, 0);
    k_gemm<3,1><<<dim3(H_/128, M_/128), 256, SMEMSZ>>>(o_b, x, out, 0);
}